// round 12
// baseline (speedup 1.0000x reference)
#include <cuda_runtime.h>
#include <math.h>

// EMD approxmatch (Fan et al.) on GB300 — round 12.
// R9 semantics + pre-packed f32x2 column/fold arrays + 256-thread blocks
// (32 rows/block, TS=512, 512 blocks = single wave). Masks: spatial bbox +
// magnitude fold-max + dead-row + arg-vote. Exact level-0. B=4, N=4096.

#define EMD_EPS 1e-9f
#define NB 4
#define MAXBN (NB * 4096)
#define TS 512          // cols per smem tile
#define THREADS 256     // 8 warps x 4 rows = 32 rows/block
#define UF_TH (-125.0f)
#define NEG_INF (-__int_as_float(0x7f800000))

typedef unsigned long long u64;

__device__ float4 g_p1[MAXBN];        // sorted (x,y,z,|p|^2) xyz1 (row loads)
__device__ float4 g_p2[MAXBN];        // sorted xyz2 (row loads)
__device__ ulonglong2 g_c1xy[MAXBN/2]; // packed x1 cols {xpair,ypair}
__device__ ulonglong2 g_c1zw[MAXBN/2]; // {zpair,wpair}
__device__ ulonglong2 g_c2xy[MAXBN/2]; // packed x2 cols
__device__ ulonglong2 g_c2zw[MAXBN/2];
__device__ float  g_rL[MAXBN];
__device__ float  g_rR[MAXBN];
__device__ u64    g_l2Rp[MAXBN/2];    // packed log2(remainR) pairs
__device__ u64    g_lgLp[MAXBN/2];    // packed log2(ratioL) pairs (raw ratioL in level-0)
__device__ u64    g_lgRp[MAXBN/2];    // packed log2(ratioR) pairs (raw ratioR in level-0)
__device__ float  g_rmL[MAXBN/4];     // per-4-row max lgL (x1)
__device__ float  g_rmR2[MAXBN/4];    // per-4-row max l2R (x2)
__device__ float  g_rmR3[MAXBN/4];    // per-4-row max lgR (x2)
__device__ float  g_cost;
__device__ float4 g_cb[2][NB * 64 * 2];

__device__ __forceinline__ float ex2f(float x) {
    float y; asm("ex2.approx.ftz.f32 %0, %1;" : "=f"(y) : "f"(x)); return y;
}
__device__ __forceinline__ float lg2f(float x) {
    float y; asm("lg2.approx.ftz.f32 %0, %1;" : "=f"(y) : "f"(x)); return y;
}
__device__ __forceinline__ float sqrtf_apx(float x) {
    float y; asm("sqrt.approx.ftz.f32 %0, %1;" : "=f"(y) : "f"(x)); return y;
}
__device__ __forceinline__ u64 pk2(float a, float b) {
    u64 r; asm("mov.b64 %0, {%1, %2};" : "=l"(r) : "f"(a), "f"(b)); return r;
}
__device__ __forceinline__ void upk2(float& a, float& b, u64 v) {
    asm("mov.b64 {%0, %1}, %2;" : "=f"(a), "=f"(b) : "l"(v));
}
__device__ __forceinline__ u64 f2fma(u64 a, u64 b, u64 c) {
    u64 d; asm("fma.rn.f32x2 %0, %1, %2, %3;" : "=l"(d) : "l"(a), "l"(b), "l"(c)); return d;
}
__device__ __forceinline__ u64 f2add(u64 a, u64 b) {
    u64 d; asm("add.rn.f32x2 %0, %1, %2;" : "=l"(d) : "l"(a), "l"(b)); return d;
}

__device__ __forceinline__ unsigned mort1(unsigned v) {
    return (v & 1u) | ((v & 2u) << 2) | ((v & 4u) << 4);
}

__device__ __forceinline__ float box_gap2(const float4* CB, int ci,
                                          float wlx, float wly, float wlz,
                                          float whx, float why, float whz) {
    float4 clo = __ldg(&CB[ci * 2]);
    float4 chi = __ldg(&CB[ci * 2 + 1]);
    float gx = fmaxf(0.0f, fmaxf(clo.x - whx, wlx - chi.x));
    float gy = fmaxf(0.0f, fmaxf(clo.y - why, wly - chi.y));
    float gz = fmaxf(0.0f, fmaxf(clo.z - whz, wlz - chi.z));
    return fmaf(gx, gx, fmaf(gy, gy, gz * gz));
}

// Counting sort by Morton cell id (8^3 cells over [-4,4]^3). grid (B,2), block 512.
__global__ void sort_kernel(const float* __restrict__ x1, const float* __restrict__ x2,
                            float multiL, float multiR, int N) {
    __shared__ unsigned hist[512];
    __shared__ unsigned scan[512];
    __shared__ unsigned offs[512];
    const int b = blockIdx.x, side = blockIdx.y, t = threadIdx.x;
    const float* px = (side ? x2 : x1) + (size_t)b * 3 * N;
    hist[t] = 0;
    __syncthreads();
    for (int i = t; i < N; i += 512) {
        float a = px[i], c = px[i + N], d = px[i + 2 * N];
        unsigned cx = (unsigned)min(7, max(0, (int)floorf(a + 4.0f)));
        unsigned cy = (unsigned)min(7, max(0, (int)floorf(c + 4.0f)));
        unsigned cz = (unsigned)min(7, max(0, (int)floorf(d + 4.0f)));
        unsigned cell = mort1(cx) | (mort1(cy) << 1) | (mort1(cz) << 2);
        atomicAdd(&hist[cell], 1u);
    }
    __syncthreads();
    scan[t] = hist[t];
    __syncthreads();
    for (int o = 1; o < 512; o <<= 1) {
        unsigned add = (t >= o) ? scan[t - o] : 0u;
        __syncthreads();
        scan[t] += add;
        __syncthreads();
    }
    offs[t] = scan[t] - hist[t];
    __syncthreads();
    for (int i = t; i < N; i += 512) {
        float a = px[i], c = px[i + N], d = px[i + 2 * N];
        unsigned cx = (unsigned)min(7, max(0, (int)floorf(a + 4.0f)));
        unsigned cy = (unsigned)min(7, max(0, (int)floorf(c + 4.0f)));
        unsigned cz = (unsigned)min(7, max(0, (int)floorf(d + 4.0f)));
        unsigned cell = mort1(cx) | (mort1(cy) << 1) | (mort1(cz) << 2);
        unsigned pos = atomicAdd(&offs[cell], 1u);
        int idx = b * N + (int)pos;
        float4 v = make_float4(a, c, d, a * a + c * c + d * d);
        if (side == 0) { g_p1[idx] = v; g_rL[idx] = multiL; }
        else           { g_p2[idx] = v; g_rR[idx] = multiR; }
    }
    if (b == 0 && side == 0 && t == 0) g_cost = 0.0f;
}

// Pack columns + chunk bboxes + initial fold state. grid (B,2), block 512.
__global__ void pack_kernel(float multiR, int N) {
    const int b = blockIdx.x, side = blockIdx.y, t = threadIdx.x;
    const int warp = t >> 5, lane = t & 31;
    const float4* P = side ? g_p2 : g_p1;
    ulonglong2* CXY = side ? g_c2xy : g_c1xy;
    ulonglong2* CZW = side ? g_c2zw : g_c1zw;
    float4* CB = g_cb[side];

    for (int p = t; p < N / 2; p += 512) {
        int j = b * N + 2 * p;
        float4 q0 = P[j], q1 = P[j + 1];
        ulonglong2 xy; xy.x = pk2(q0.x, q1.x); xy.y = pk2(q0.y, q1.y);
        ulonglong2 zw; zw.x = pk2(q0.z, q1.z); zw.y = pk2(q0.w, q1.w);
        CXY[b * (N / 2) + p] = xy;
        CZW[b * (N / 2) + p] = zw;
    }
    if (side == 1) {
        float l2r = lg2f(multiR);
        u64 l2rp = pk2(l2r, l2r);
        for (int p = t; p < N / 2; p += 512) g_l2Rp[b * (N / 2) + p] = l2rp;
        for (int i = t; i < N / 4; i += 512) g_rmR2[b * (N / 4) + i] = l2r;
    }
    for (int c = warp; c < 64; c += 16) {
        int j = b * N + c * 64 + lane;
        float4 p0 = P[j], p1 = P[j + 32];
        float lx = fminf(p0.x, p1.x), hx = fmaxf(p0.x, p1.x);
        float ly = fminf(p0.y, p1.y), hy = fmaxf(p0.y, p1.y);
        float lz = fminf(p0.z, p1.z), hz = fmaxf(p0.z, p1.z);
#pragma unroll
        for (int o = 16; o; o >>= 1) {
            lx = fminf(lx, __shfl_xor_sync(0xffffffffu, lx, o));
            hx = fmaxf(hx, __shfl_xor_sync(0xffffffffu, hx, o));
            ly = fminf(ly, __shfl_xor_sync(0xffffffffu, ly, o));
            hy = fmaxf(hy, __shfl_xor_sync(0xffffffffu, hy, o));
            lz = fminf(lz, __shfl_xor_sync(0xffffffffu, lz, o));
            hz = fmaxf(hz, __shfl_xor_sync(0xffffffffu, hz, o));
        }
        if (lane == 0) {
            CB[(b * 64 + c) * 2]     = make_float4(lx, ly, lz, 0.0f);
            CB[(b * 64 + c) * 2 + 1] = make_float4(hx, hy, hz, 0.0f);
        }
    }
}

// ---------------- unified P1/P2 (all sweeps) ----------------
// MODE 1: rows=x1 (rL), cols=x2, fold=g_l2Rp, cm=g_rmR2; writes lgLp + rmL.
// MODE 2: rows=x2 (rR), cols=x1, fold=g_lgLp, cm=g_rmL; writes lgRp,l2Rp,rR + rmR2,rmR3.
template <int MODE>
__global__ void __launch_bounds__(THREADS, 4) pass12_kernel(float klg, int N) {
    __shared__ ulonglong2 s_xy[TS / 2];
    __shared__ ulonglong2 s_zf[TS / 2];
    __shared__ float s_cm[64];
    __shared__ unsigned s_bm[8][2];
    const int b = blockIdx.y, base = b * N, pbase = b * (N / 2);
    const int t = threadIdx.x, warp = t >> 5, lane = t & 31;
    const int r0 = blockIdx.x * 32 + warp * 4;

    const float4* P        = (MODE == 1) ? g_p1 : g_p2;
    const ulonglong2* CXY  = (MODE == 1) ? g_c2xy : g_c1xy;
    const ulonglong2* CZW  = (MODE == 1) ? g_c2zw : g_c1zw;
    const u64* FOLD        = (MODE == 1) ? g_l2Rp : g_lgLp;
    const float4* CB       = (MODE == 1) ? g_cb[1] : g_cb[0];
    const float*  RM       = (MODE == 1) ? g_rmR2 : g_rmL;

    if (t < 64) {
        float m = NEG_INF;
#pragma unroll
        for (int k = 0; k < 16; k++) m = fmaxf(m, RM[b * (N / 4) + t * 16 + k]);
        s_cm[t] = m;
    }

    u64 rx[4], ry[4], rz[4], rw[4], acc[4];
    float4 A[4];
    float rowv[4];
#pragma unroll
    for (int r = 0; r < 4; r++) {
        A[r] = P[base + r0 + r];
        rowv[r] = (MODE == 1) ? g_rL[base + r0 + r] : g_rR[base + r0 + r];
    }
#pragma unroll
    for (int r = 0; r < 4; r++) {
        float kx = klg * -2.0f * A[r].x, ky = klg * -2.0f * A[r].y, kz = klg * -2.0f * A[r].z;
        float kw = klg * A[r].w;
        rx[r] = pk2(kx, kx); ry[r] = pk2(ky, ky); rz[r] = pk2(kz, kz); rw[r] = pk2(kw, kw);
        acc[r] = 0ull;
    }
    bool rowsDead = (fmaxf(fmaxf(rowv[0], rowv[1]), fmaxf(rowv[2], rowv[3])) == 0.0f);
    __syncthreads();

    u64 wm;
    if (rowsDead) {
        __ballot_sync(0xffffffffu, 1);
        wm = ~0ull;
        if (lane == 0) { s_bm[warp][0] = 0xffffffffu; s_bm[warp][1] = 0xffffffffu; }
    } else {
        float wlx = fminf(fminf(A[0].x, A[1].x), fminf(A[2].x, A[3].x));
        float whx = fmaxf(fmaxf(A[0].x, A[1].x), fmaxf(A[2].x, A[3].x));
        float wly = fminf(fminf(A[0].y, A[1].y), fminf(A[2].y, A[3].y));
        float why = fmaxf(fmaxf(A[0].y, A[1].y), fmaxf(A[2].y, A[3].y));
        float wlz = fminf(fminf(A[0].z, A[1].z), fminf(A[2].z, A[3].z));
        float whz = fmaxf(fmaxf(A[0].z, A[1].z), fmaxf(A[2].z, A[3].z));
        float g0 = box_gap2(CB, b * 64 + lane,      wlx, wly, wlz, whx, why, whz);
        float g1 = box_gap2(CB, b * 64 + lane + 32, wlx, wly, wlz, whx, why, whz);
        bool k0 = fmaf(klg, g0, s_cm[lane])      < UF_TH;
        bool k1 = fmaf(klg, g1, s_cm[lane + 32]) < UF_TH;
        unsigned lo = __ballot_sync(0xffffffffu, k0);
        unsigned hi = __ballot_sync(0xffffffffu, k1);
        wm = ((u64)hi << 32) | lo;
        if (lane == 0) { s_bm[warp][0] = lo; s_bm[warp][1] = hi; }
    }
    __syncthreads();
    unsigned blo = 0xffffffffu, bhi = 0xffffffffu;
#pragma unroll
    for (int w = 0; w < 8; w++) { blo &= s_bm[w][0]; bhi &= s_bm[w][1]; }
    u64 bm = ((u64)bhi << 32) | blo;
    const u64 klg2 = pk2(klg, klg);

    for (int c = 0; c < N; c += TS) {
        const int tb = c >> 6;   // 8 chunks per tile
        if (((bm >> tb) & 0xFFull) == 0xFFull) continue;
        {
            int p = pbase + c / 2 + t;
            ulonglong2 xy = CXY[p];
            ulonglong2 zw = CZW[p];
            ulonglong2 zf; zf.x = zw.x; zf.y = f2fma(klg2, zw.y, FOLD[p]);
            s_xy[t] = xy; s_zf[t] = zf;
        }
        __syncthreads();
#pragma unroll
        for (int it = 0; it < TS / 64; it++) {
            if ((wm >> (tb + it)) & 1ull) continue;
            int p = it * 32 + lane;
            ulonglong2 xy = s_xy[p];
            ulonglong2 zf = s_zf[p];
            u64 a0 = f2fma(rz[0], zf.x, f2fma(ry[0], xy.y, f2fma(rx[0], xy.x, f2add(zf.y, rw[0]))));
            u64 a1 = f2fma(rz[1], zf.x, f2fma(ry[1], xy.y, f2fma(rx[1], xy.x, f2add(zf.y, rw[1]))));
            u64 a2 = f2fma(rz[2], zf.x, f2fma(ry[2], xy.y, f2fma(rx[2], xy.x, f2add(zf.y, rw[2]))));
            u64 a3 = f2fma(rz[3], zf.x, f2fma(ry[3], xy.y, f2fma(rx[3], xy.x, f2add(zf.y, rw[3]))));
            float e0, e1, e2, e3, e4, e5, e6, e7;
            upk2(e0, e1, a0); upk2(e2, e3, a1); upk2(e4, e5, a2); upk2(e6, e7, a3);
            float m0 = fmaxf(fmaxf(e0, e1), fmaxf(e2, e3));
            float m1 = fmaxf(fmaxf(e4, e5), fmaxf(e6, e7));
            if (__all_sync(0xffffffffu, fmaxf(m0, m1) < UF_TH)) continue;
            acc[0] = f2add(acc[0], pk2(ex2f(e0), ex2f(e1)));
            acc[1] = f2add(acc[1], pk2(ex2f(e2), ex2f(e3)));
            acc[2] = f2add(acc[2], pk2(ex2f(e4), ex2f(e5)));
            acc[3] = f2add(acc[3], pk2(ex2f(e6), ex2f(e7)));
        }
        __syncthreads();
    }

#pragma unroll
    for (int off = 16; off; off >>= 1) {
#pragma unroll
        for (int r = 0; r < 4; r++)
            acc[r] = f2add(acc[r], __shfl_down_sync(0xffffffffu, acc[r], off));
    }
    if (lane == 0) {
        int idx4 = (base + r0) >> 2;
        int ip = (base + r0) >> 1;
        if (MODE == 1) {
            float lg[4];
            float mx = NEG_INF;
#pragma unroll
            for (int r = 0; r < 4; r++) {
                float lo, hi; upk2(lo, hi, acc[r]);
                lg[r] = lg2f(rowv[r] / (EMD_EPS + (lo + hi)));
                mx = fmaxf(mx, lg[r]);
            }
            g_lgLp[ip]     = pk2(lg[0], lg[1]);
            g_lgLp[ip + 1] = pk2(lg[2], lg[3]);
            g_rmL[idx4] = mx;
        } else {
            float lgr[4], l2r[4];
            float mx2 = NEG_INF, mx3 = NEG_INF;
#pragma unroll
            for (int r = 0; r < 4; r++) {
                float lo, hi; upk2(lo, hi, acc[r]);
                float a = lo + hi;
                float rr   = rowv[r];
                float sumr = rr * a;
                float cons = fminf(rr / (sumr + EMD_EPS), 1.0f);
                float nrr  = fmaxf(0.0f, rr - sumr);
                lgr[r] = lg2f(cons * rr);
                l2r[r] = lg2f(nrr);
                g_rR[base + r0 + r] = nrr;
                mx2 = fmaxf(mx2, l2r[r]);
                mx3 = fmaxf(mx3, lgr[r]);
            }
            g_lgRp[ip]     = pk2(lgr[0], lgr[1]);
            g_lgRp[ip + 1] = pk2(lgr[2], lgr[3]);
            g_l2Rp[ip]     = pk2(l2r[0], l2r[1]);
            g_l2Rp[ip + 1] = pk2(l2r[2], l2r[3]);
            g_rmR2[idx4] = mx2;
            g_rmR3[idx4] = mx3;
        }
    }
}

// ---------------- unified P3 (all sweeps) ----------------
__global__ void __launch_bounds__(THREADS, 4) pass3_kernel(float klg, int N) {
    __shared__ ulonglong2 s_xy[TS / 2];
    __shared__ ulonglong2 s_zw[TS / 2];
    __shared__ u64        s_lq[TS / 2];
    __shared__ float s_cm[64];
    __shared__ unsigned s_bm[8][2];
    const int b = blockIdx.y, base = b * N, pbase = b * (N / 2);
    const int t = threadIdx.x, warp = t >> 5, lane = t & 31;
    const int r0 = blockIdx.x * 32 + warp * 4;

    if (t < 64) {
        float m = NEG_INF;
#pragma unroll
        for (int k = 0; k < 16; k++) m = fmaxf(m, g_rmR3[b * (N / 4) + t * 16 + k]);
        s_cm[t] = m;
    }

    u64 rx[4], ry[4], rz[4], rw[4], wa[4], cs[4];
    float lgL[4];
    float4 A[4];
    {
        u64 l01 = g_lgLp[(base + r0) >> 1];
        u64 l23 = g_lgLp[((base + r0) >> 1) + 1];
        upk2(lgL[0], lgL[1], l01);
        upk2(lgL[2], lgL[3], l23);
    }
#pragma unroll
    for (int r = 0; r < 4; r++) {
        A[r] = g_p1[base + r0 + r];
        rx[r] = pk2(-2.0f * A[r].x, -2.0f * A[r].x);
        ry[r] = pk2(-2.0f * A[r].y, -2.0f * A[r].y);
        rz[r] = pk2(-2.0f * A[r].z, -2.0f * A[r].z);
        rw[r] = pk2(A[r].w, A[r].w);
        wa[r] = 0ull; cs[r] = 0ull;
    }
    float wmaxL = fmaxf(fmaxf(lgL[0], lgL[1]), fmaxf(lgL[2], lgL[3]));
    bool rowsDead = (wmaxL < -126.0f);
    __syncthreads();

    u64 wm;
    if (rowsDead) {
        __ballot_sync(0xffffffffu, 1);
        wm = ~0ull;
        if (lane == 0) { s_bm[warp][0] = 0xffffffffu; s_bm[warp][1] = 0xffffffffu; }
    } else {
        float wlx = fminf(fminf(A[0].x, A[1].x), fminf(A[2].x, A[3].x));
        float whx = fmaxf(fmaxf(A[0].x, A[1].x), fmaxf(A[2].x, A[3].x));
        float wly = fminf(fminf(A[0].y, A[1].y), fminf(A[2].y, A[3].y));
        float why = fmaxf(fmaxf(A[0].y, A[1].y), fmaxf(A[2].y, A[3].y));
        float wlz = fminf(fminf(A[0].z, A[1].z), fminf(A[2].z, A[3].z));
        float whz = fmaxf(fmaxf(A[0].z, A[1].z), fmaxf(A[2].z, A[3].z));
        float g0 = box_gap2(g_cb[1], b * 64 + lane,      wlx, wly, wlz, whx, why, whz);
        float g1 = box_gap2(g_cb[1], b * 64 + lane + 32, wlx, wly, wlz, whx, why, whz);
        bool k0 = fmaf(klg, g0, s_cm[lane]      + wmaxL) < UF_TH;
        bool k1 = fmaf(klg, g1, s_cm[lane + 32] + wmaxL) < UF_TH;
        unsigned lo = __ballot_sync(0xffffffffu, k0);
        unsigned hi = __ballot_sync(0xffffffffu, k1);
        wm = ((u64)hi << 32) | lo;
        if (lane == 0) { s_bm[warp][0] = lo; s_bm[warp][1] = hi; }
    }
    __syncthreads();
    unsigned blo = 0xffffffffu, bhi = 0xffffffffu;
#pragma unroll
    for (int w = 0; w < 8; w++) { blo &= s_bm[w][0]; bhi &= s_bm[w][1]; }
    u64 bm = ((u64)bhi << 32) | blo;
    const u64 klg2 = pk2(klg, klg);

    for (int c = 0; c < N; c += TS) {
        const int tb = c >> 6;
        if (((bm >> tb) & 0xFFull) == 0xFFull) continue;
        {
            int p = pbase + c / 2 + t;
            s_xy[t] = g_c2xy[p];
            s_zw[t] = g_c2zw[p];
            s_lq[t] = g_lgRp[p];
        }
        __syncthreads();
#pragma unroll
        for (int it = 0; it < TS / 64; it++) {
            if ((wm >> (tb + it)) & 1ull) continue;
            int p = it * 32 + lane;
            ulonglong2 xy = s_xy[p];
            ulonglong2 zw = s_zw[p];
            u64 lq2 = s_lq[p];
            u64 d0 = f2fma(rz[0], zw.x, f2fma(ry[0], xy.y, f2fma(rx[0], xy.x, f2add(zw.y, rw[0]))));
            u64 d1 = f2fma(rz[1], zw.x, f2fma(ry[1], xy.y, f2fma(rx[1], xy.x, f2add(zw.y, rw[1]))));
            u64 d2 = f2fma(rz[2], zw.x, f2fma(ry[2], xy.y, f2fma(rx[2], xy.x, f2add(zw.y, rw[2]))));
            u64 d3 = f2fma(rz[3], zw.x, f2fma(ry[3], xy.y, f2fma(rx[3], xy.x, f2add(zw.y, rw[3]))));
            u64 a0 = f2fma(klg2, d0, lq2);
            u64 a1 = f2fma(klg2, d1, lq2);
            u64 a2 = f2fma(klg2, d2, lq2);
            u64 a3 = f2fma(klg2, d3, lq2);
            float f0, f1, f2v, f3v, f4, f5, f6, f7;
            upk2(f0, f1, a0); upk2(f2v, f3v, a1); upk2(f4, f5, a2); upk2(f6, f7, a3);
            float m0 = fmaxf(fmaxf(f0, f1), fmaxf(f2v, f3v));
            float m1 = fmaxf(fmaxf(f4, f5), fmaxf(f6, f7));
            if (__all_sync(0xffffffffu, fmaxf(m0, m1) < UF_TH)) continue;
#pragma unroll
            for (int r = 0; r < 4; r++) {
                u64 dd = (r == 0) ? d0 : (r == 1) ? d1 : (r == 2) ? d2 : d3;
                float av0, av1;
                if (r == 0)      { av0 = f0;  av1 = f1; }
                else if (r == 1) { av0 = f2v; av1 = f3v; }
                else if (r == 2) { av0 = f4;  av1 = f5; }
                else             { av0 = f6;  av1 = f7; }
                float dl, dh; upk2(dl, dh, dd);
                float c0 = fmaxf(dl, 1e-20f), c1 = fmaxf(dh, 1e-20f);
                float w0 = ex2f(av0), w1 = ex2f(av1);
                float s0 = sqrtf_apx(c0), s1 = sqrtf_apx(c1);
                u64 wv = pk2(w0, w1);
                wa[r] = f2add(wa[r], wv);
                cs[r] = f2fma(wv, pk2(s0, s1), cs[r]);
            }
        }
        __syncthreads();
    }

#pragma unroll
    for (int off = 16; off; off >>= 1) {
#pragma unroll
        for (int r = 0; r < 4; r++) {
            wa[r] = f2add(wa[r], __shfl_down_sync(0xffffffffu, wa[r], off));
            cs[r] = f2add(cs[r], __shfl_down_sync(0xffffffffu, cs[r], off));
        }
    }
    if (lane == 0 && !rowsDead) {
        float cost = 0.0f;
#pragma unroll
        for (int r = 0; r < 4; r++) {
            int idx = base + r0 + r;
            float eL = ex2f(lgL[r]);
            float wl, wh; upk2(wl, wh, wa[r]);
            float cl, ch; upk2(cl, ch, cs[r]);
            g_rL[idx] = fmaxf(0.0f, g_rL[idx] - eL * (wl + wh));
            cost = fmaf(eL, cl + ch, cost);
        }
        atomicAdd(&g_cost, cost);
    }
}

// ---------------- level == 0 sweep (exact) ----------------
__global__ void level0_prep(int N) {
    __shared__ float red[256];
    __shared__ float Tv, Uv;
    const int b = blockIdx.x, base = b * N, t = threadIdx.x;
    float ts = 0.0f, us = 0.0f;
    for (int i = t; i < N; i += 256) { ts += g_rR[base + i]; us += g_rL[base + i]; }
    red[t] = ts; __syncthreads();
    for (int o = 128; o; o >>= 1) { if (t < o) red[t] += red[t + o]; __syncthreads(); }
    if (t == 0) Tv = red[0];
    __syncthreads();
    red[t] = us; __syncthreads();
    for (int o = 128; o; o >>= 1) { if (t < o) red[t] += red[t + o]; __syncthreads(); }
    if (t == 0) Uv = red[0];
    __syncthreads();
    float scale = 1.0f / (EMD_EPS + Tv);
    float S = Uv * scale;
    for (int g = t; g < N / 4; g += 256) {
        float rl[4], rr4[4];
        float mxR = 0.0f;
#pragma unroll
        for (int k = 0; k < 4; k++) {
            int i = base + g * 4 + k;
            rl[k] = g_rL[i] * scale;                      // raw ratioL
            float rr   = g_rR[i];
            float sumr = rr * S;
            float cons = fminf(rr / (sumr + EMD_EPS), 1.0f);
            rr4[k] = cons * rr;                           // raw ratioR
            mxR = fmaxf(mxR, rr4[k]);
        }
        int ip = (base + g * 4) >> 1;
        g_lgLp[ip]     = pk2(rl[0], rl[1]);
        g_lgLp[ip + 1] = pk2(rl[2], rl[3]);
        g_lgRp[ip]     = pk2(rr4[0], rr4[1]);
        g_lgRp[ip + 1] = pk2(rr4[2], rr4[3]);
        g_rmR3[b * (N / 4) + g] = mxR;
    }
}

__global__ void __launch_bounds__(THREADS, 4) level0_cost(int N) {
    __shared__ ulonglong2 s_xy[TS / 2];
    __shared__ ulonglong2 s_zw[TS / 2];
    __shared__ u64        s_rr[TS / 2];
    __shared__ float s_cm[64];
    __shared__ unsigned s_bm[8][2];
    const int b = blockIdx.y, base = b * N, pbase = b * (N / 2);
    const int t = threadIdx.x, warp = t >> 5, lane = t & 31;
    const int r0 = blockIdx.x * 32 + warp * 4;

    if (t < 64) {
        float m = 0.0f;
#pragma unroll
        for (int k = 0; k < 16; k++) m = fmaxf(m, g_rmR3[b * (N / 4) + t * 16 + k]);
        s_cm[t] = m;
    }

    u64 rx[4], ry[4], rz[4], rw[4], cs[4];
    float rl[4];
    {
        u64 l01 = g_lgLp[(base + r0) >> 1];
        u64 l23 = g_lgLp[((base + r0) >> 1) + 1];
        upk2(rl[0], rl[1], l01);
        upk2(rl[2], rl[3], l23);
    }
#pragma unroll
    for (int r = 0; r < 4; r++) {
        float4 A = g_p1[base + r0 + r];
        rx[r] = pk2(-2.0f * A.x, -2.0f * A.x);
        ry[r] = pk2(-2.0f * A.y, -2.0f * A.y);
        rz[r] = pk2(-2.0f * A.z, -2.0f * A.z);
        rw[r] = pk2(A.w, A.w);
        cs[r] = 0ull;
    }
    bool rowsDead = (fmaxf(fmaxf(rl[0], rl[1]), fmaxf(rl[2], rl[3])) == 0.0f);
    __syncthreads();

    u64 wm;
    {
        bool k0 = rowsDead || (s_cm[lane]      == 0.0f);
        bool k1 = rowsDead || (s_cm[lane + 32] == 0.0f);
        unsigned lo = __ballot_sync(0xffffffffu, k0);
        unsigned hi = __ballot_sync(0xffffffffu, k1);
        wm = ((u64)hi << 32) | lo;
        if (lane == 0) { s_bm[warp][0] = lo; s_bm[warp][1] = hi; }
    }
    __syncthreads();
    unsigned blo = 0xffffffffu, bhi = 0xffffffffu;
#pragma unroll
    for (int w = 0; w < 8; w++) { blo &= s_bm[w][0]; bhi &= s_bm[w][1]; }
    u64 bm = ((u64)bhi << 32) | blo;

    for (int c = 0; c < N; c += TS) {
        const int tb = c >> 6;
        if (((bm >> tb) & 0xFFull) == 0xFFull) continue;
        {
            int p = pbase + c / 2 + t;
            s_xy[t] = g_c2xy[p];
            s_zw[t] = g_c2zw[p];
            s_rr[t] = g_lgRp[p];
        }
        __syncthreads();
#pragma unroll
        for (int it = 0; it < TS / 64; it++) {
            if ((wm >> (tb + it)) & 1ull) continue;
            int p = it * 32 + lane;
            ulonglong2 xy = s_xy[p];
            ulonglong2 zw = s_zw[p];
            u64 rr2 = s_rr[p];
            if (__all_sync(0xffffffffu, rr2 == 0ull)) continue;
#pragma unroll
            for (int r = 0; r < 4; r++) {
                u64 dd = f2fma(rz[r], zw.x, f2fma(ry[r], xy.y, f2fma(rx[r], xy.x, f2add(zw.y, rw[r]))));
                float dl, dh; upk2(dl, dh, dd);
                float s0 = sqrtf_apx(fmaxf(dl, 1e-20f));
                float s1 = sqrtf_apx(fmaxf(dh, 1e-20f));
                cs[r] = f2fma(rr2, pk2(s0, s1), cs[r]);
            }
        }
        __syncthreads();
    }

#pragma unroll
    for (int off = 16; off; off >>= 1) {
#pragma unroll
        for (int r = 0; r < 4; r++)
            cs[r] = f2add(cs[r], __shfl_down_sync(0xffffffffu, cs[r], off));
    }
    if (lane == 0 && !rowsDead) {
        float cost = 0.0f;
#pragma unroll
        for (int r = 0; r < 4; r++) {
            float cl, ch; upk2(cl, ch, cs[r]);
            cost = fmaf(rl[r], cl + ch, cost);
        }
        atomicAdd(&g_cost, cost);
    }
}

__global__ void final_kernel(float* out, float inv) {
    out[0] = g_cost * inv;
}

extern "C" void kernel_launch(void* const* d_in, const int* in_sizes, int n_in,
                              void* d_out, int out_size) {
    const float* x1 = (const float*)d_in[0];
    const float* x2 = (const float*)d_in[1];
    const int B = NB;
    const int N = in_sizes[0] / (3 * B);   // 4096
    const int n = N, m = N;

    float multiL, multiR;
    if (n >= m) { multiL = 1.0f; multiR = (float)(n / m); }
    else        { multiL = (float)(m / n); multiR = 1.0f; }

    sort_kernel<<<dim3(B, 2), 512>>>(x1, x2, multiL, multiR, N);
    pack_kernel<<<dim3(B, 2), 512>>>(multiR, N);

    dim3 grid(N / 32, B);   // 128 x 4 = 512 blocks, single wave at 4/SM
    const float LOG2E = 1.4426950408889634f;
    for (int s = 0; s < 9; s++) {
        float level = -ldexpf(1.0f, 2 * (7 - s));   // -4^(7-s); s=8 -> -0.25
        float klg = level * LOG2E;
        pass12_kernel<1><<<grid, THREADS>>>(klg, N);
        pass12_kernel<2><<<grid, THREADS>>>(klg, N);
        pass3_kernel<<<grid, THREADS>>>(klg, N);
    }
    level0_prep<<<B, 256>>>(N);
    level0_cost<<<grid, THREADS>>>(N);

    float mn = (float)((n < m ? n : m) * B);
    final_kernel<<<1, 1>>>((float*)d_out, 1.0f / mn);
}

// round 13
// speedup vs baseline: 1.6758x; 1.6758x over previous
#include <cuda_runtime.h>
#include <math.h>

// EMD approxmatch (Fan et al.) on GB300 — round 13.
// R9 (best) + fused P3(s)+P1(s+1) kernel: one column sweep computes dist once
// and serves both passes (P3 flow/cost at level s, P1 row-sums at level s+1),
// with per-side pruning masks. 22 launches. B=4, N=4096.

#define EMD_EPS 1e-9f
#define NB 4
#define MAXBN (NB * 4096)
#define TS 256
#define RPB 16
#define UF_TH (-125.0f)
#define NEG_INF (-__int_as_float(0x7f800000))

typedef unsigned long long u64;

__device__ float4 g_p1[MAXBN];
__device__ float4 g_p2[MAXBN];
__device__ float  g_rL[MAXBN];
__device__ float  g_rR[MAXBN];
__device__ float  g_l2R[MAXBN];    // log2(remainR)
__device__ float  g_lgL[MAXBN];    // log2(ratioL)  (raw ratioL during level-0)
__device__ float  g_lgR[MAXBN];    // log2(ratioR)  (raw ratioR during level-0)
__device__ float  g_rmL[MAXBN/4];  // per-4-row max lgL (x1)
__device__ float  g_rmR2[MAXBN/4]; // per-4-row max l2R (x2)
__device__ float  g_rmR3[MAXBN/4]; // per-4-row max lgR (x2)
__device__ float  g_cost;
__device__ float4 g_cb[2][NB * 64 * 2];

__device__ __forceinline__ float ex2f(float x) {
    float y; asm("ex2.approx.ftz.f32 %0, %1;" : "=f"(y) : "f"(x)); return y;
}
__device__ __forceinline__ float lg2f(float x) {
    float y; asm("lg2.approx.ftz.f32 %0, %1;" : "=f"(y) : "f"(x)); return y;
}
__device__ __forceinline__ float sqrtf_apx(float x) {
    float y; asm("sqrt.approx.ftz.f32 %0, %1;" : "=f"(y) : "f"(x)); return y;
}
__device__ __forceinline__ u64 pk2(float a, float b) {
    u64 r; asm("mov.b64 %0, {%1, %2};" : "=l"(r) : "f"(a), "f"(b)); return r;
}
__device__ __forceinline__ void upk2(float& a, float& b, u64 v) {
    asm("mov.b64 {%0, %1}, %2;" : "=f"(a), "=f"(b) : "l"(v));
}
__device__ __forceinline__ u64 f2fma(u64 a, u64 b, u64 c) {
    u64 d; asm("fma.rn.f32x2 %0, %1, %2, %3;" : "=l"(d) : "l"(a), "l"(b), "l"(c)); return d;
}
__device__ __forceinline__ u64 f2add(u64 a, u64 b) {
    u64 d; asm("add.rn.f32x2 %0, %1, %2;" : "=l"(d) : "l"(a), "l"(b)); return d;
}

__device__ __forceinline__ unsigned mort1(unsigned v) {
    return (v & 1u) | ((v & 2u) << 2) | ((v & 4u) << 4);
}

__device__ __forceinline__ float box_gap2(const float4* CB, int ci,
                                          float wlx, float wly, float wlz,
                                          float whx, float why, float whz) {
    float4 clo = __ldg(&CB[ci * 2]);
    float4 chi = __ldg(&CB[ci * 2 + 1]);
    float gx = fmaxf(0.0f, fmaxf(clo.x - whx, wlx - chi.x));
    float gy = fmaxf(0.0f, fmaxf(clo.y - why, wly - chi.y));
    float gz = fmaxf(0.0f, fmaxf(clo.z - whz, wlz - chi.z));
    return fmaf(gx, gx, fmaf(gy, gy, gz * gz));
}

// Counting sort by Morton cell id. grid (B,2), block 512.
__global__ void sort_kernel(const float* __restrict__ x1, const float* __restrict__ x2,
                            float multiL, float multiR, int N) {
    __shared__ unsigned hist[512];
    __shared__ unsigned scan[512];
    __shared__ unsigned offs[512];
    const int b = blockIdx.x, side = blockIdx.y, t = threadIdx.x;
    const float* px = (side ? x2 : x1) + (size_t)b * 3 * N;
    hist[t] = 0;
    __syncthreads();
    for (int i = t; i < N; i += 512) {
        float a = px[i], c = px[i + N], d = px[i + 2 * N];
        unsigned cx = (unsigned)min(7, max(0, (int)floorf(a + 4.0f)));
        unsigned cy = (unsigned)min(7, max(0, (int)floorf(c + 4.0f)));
        unsigned cz = (unsigned)min(7, max(0, (int)floorf(d + 4.0f)));
        unsigned cell = mort1(cx) | (mort1(cy) << 1) | (mort1(cz) << 2);
        atomicAdd(&hist[cell], 1u);
    }
    __syncthreads();
    scan[t] = hist[t];
    __syncthreads();
    for (int o = 1; o < 512; o <<= 1) {
        unsigned add = (t >= o) ? scan[t - o] : 0u;
        __syncthreads();
        scan[t] += add;
        __syncthreads();
    }
    offs[t] = scan[t] - hist[t];
    __syncthreads();
    for (int i = t; i < N; i += 512) {
        float a = px[i], c = px[i + N], d = px[i + 2 * N];
        unsigned cx = (unsigned)min(7, max(0, (int)floorf(a + 4.0f)));
        unsigned cy = (unsigned)min(7, max(0, (int)floorf(c + 4.0f)));
        unsigned cz = (unsigned)min(7, max(0, (int)floorf(d + 4.0f)));
        unsigned cell = mort1(cx) | (mort1(cy) << 1) | (mort1(cz) << 2);
        unsigned pos = atomicAdd(&offs[cell], 1u);
        int idx = b * N + (int)pos;
        float4 v = make_float4(a, c, d, a * a + c * c + d * d);
        if (side == 0) { g_p1[idx] = v; g_rL[idx] = multiL; }
        else           { g_p2[idx] = v; g_rR[idx] = multiR; g_l2R[idx] = lg2f(multiR); }
    }
    if (side == 1) {
        for (int i = t; i < N / 4; i += 512) g_rmR2[b * (N / 4) + i] = lg2f(multiR);
    }
    if (b == 0 && side == 0 && t == 0) g_cost = 0.0f;
}

// Chunk (64-pt) bboxes. grid (B,2), block 512.
__global__ void bbox_kernel(int N) {
    const int b = blockIdx.x, side = blockIdx.y, t = threadIdx.x;
    const int warp = t >> 5, lane = t & 31;
    const float4* P = side ? g_p2 : g_p1;
    float4* CB = g_cb[side];
    for (int c = warp; c < 64; c += 16) {
        int j = b * N + c * 64 + lane;
        float4 p0 = P[j], p1 = P[j + 32];
        float lx = fminf(p0.x, p1.x), hx = fmaxf(p0.x, p1.x);
        float ly = fminf(p0.y, p1.y), hy = fmaxf(p0.y, p1.y);
        float lz = fminf(p0.z, p1.z), hz = fmaxf(p0.z, p1.z);
#pragma unroll
        for (int o = 16; o; o >>= 1) {
            lx = fminf(lx, __shfl_xor_sync(0xffffffffu, lx, o));
            hx = fmaxf(hx, __shfl_xor_sync(0xffffffffu, hx, o));
            ly = fminf(ly, __shfl_xor_sync(0xffffffffu, ly, o));
            hy = fmaxf(hy, __shfl_xor_sync(0xffffffffu, hy, o));
            lz = fminf(lz, __shfl_xor_sync(0xffffffffu, lz, o));
            hz = fmaxf(hz, __shfl_xor_sync(0xffffffffu, hz, o));
        }
        if (lane == 0) {
            CB[(b * 64 + c) * 2]     = make_float4(lx, ly, lz, 0.0f);
            CB[(b * 64 + c) * 2 + 1] = make_float4(hx, hy, hz, 0.0f);
        }
    }
}

// ---------------- P1/P2 kernel (R9 verbatim) ----------------
template <int MODE>
__global__ void __launch_bounds__(128, 6) pass12_kernel(float klg, int N) {
    __shared__ ulonglong2 s_xy[TS / 2];
    __shared__ ulonglong2 s_zf[TS / 2];
    __shared__ float s_cm[64];
    __shared__ unsigned s_bm[4][2];
    const int b = blockIdx.y, base = b * N;
    const int t = threadIdx.x, warp = t >> 5, lane = t & 31;
    const int r0 = blockIdx.x * RPB + warp * 4;

    const float4* P    = (MODE == 1) ? g_p1 : g_p2;
    const float4* Q    = (MODE == 1) ? g_p2 : g_p1;
    const float4* CB   = (MODE == 1) ? g_cb[1] : g_cb[0];
    const float*  FOLD = (MODE == 1) ? g_l2R : g_lgL;
    const float*  RM   = (MODE == 1) ? g_rmR2 : g_rmL;

    if (t < 64) {
        float m = NEG_INF;
#pragma unroll
        for (int k = 0; k < 16; k++) m = fmaxf(m, RM[b * (N / 4) + t * 16 + k]);
        s_cm[t] = m;
    }

    u64 rx[4], ry[4], rz[4], rw[4], acc[4];
    float4 A[4];
    float rowv[4];
#pragma unroll
    for (int r = 0; r < 4; r++) {
        A[r] = P[base + r0 + r];
        rowv[r] = (MODE == 1) ? g_rL[base + r0 + r] : g_rR[base + r0 + r];
    }
#pragma unroll
    for (int r = 0; r < 4; r++) {
        float kx = klg * -2.0f * A[r].x, ky = klg * -2.0f * A[r].y, kz = klg * -2.0f * A[r].z;
        float kw = klg * A[r].w;
        rx[r] = pk2(kx, kx); ry[r] = pk2(ky, ky); rz[r] = pk2(kz, kz); rw[r] = pk2(kw, kw);
        acc[r] = 0ull;
    }
    bool rowsDead = (fmaxf(fmaxf(rowv[0], rowv[1]), fmaxf(rowv[2], rowv[3])) == 0.0f);
    __syncthreads();

    u64 wm;
    if (rowsDead) {
        __ballot_sync(0xffffffffu, 1);
        wm = ~0ull;
        if (lane == 0) { s_bm[warp][0] = 0xffffffffu; s_bm[warp][1] = 0xffffffffu; }
    } else {
        float wlx = fminf(fminf(A[0].x, A[1].x), fminf(A[2].x, A[3].x));
        float whx = fmaxf(fmaxf(A[0].x, A[1].x), fmaxf(A[2].x, A[3].x));
        float wly = fminf(fminf(A[0].y, A[1].y), fminf(A[2].y, A[3].y));
        float why = fmaxf(fmaxf(A[0].y, A[1].y), fmaxf(A[2].y, A[3].y));
        float wlz = fminf(fminf(A[0].z, A[1].z), fminf(A[2].z, A[3].z));
        float whz = fmaxf(fmaxf(A[0].z, A[1].z), fmaxf(A[2].z, A[3].z));
        float g0 = box_gap2(CB, b * 64 + lane,      wlx, wly, wlz, whx, why, whz);
        float g1 = box_gap2(CB, b * 64 + lane + 32, wlx, wly, wlz, whx, why, whz);
        bool k0 = fmaf(klg, g0, s_cm[lane])      < UF_TH;
        bool k1 = fmaf(klg, g1, s_cm[lane + 32]) < UF_TH;
        unsigned lo = __ballot_sync(0xffffffffu, k0);
        unsigned hi = __ballot_sync(0xffffffffu, k1);
        wm = ((u64)hi << 32) | lo;
        if (lane == 0) { s_bm[warp][0] = lo; s_bm[warp][1] = hi; }
    }
    __syncthreads();
    u64 bm = (((u64)(s_bm[0][1] & s_bm[1][1] & s_bm[2][1] & s_bm[3][1])) << 32) |
             (u64)(s_bm[0][0] & s_bm[1][0] & s_bm[2][0] & s_bm[3][0]);

    for (int c = 0; c < N; c += TS) {
        const int tb = c >> 6;
        if (((bm >> tb) & 0xFull) == 0xFull) continue;
        {
            int j = base + c + 2 * t;
            float4 q0 = Q[j], q1 = Q[j + 1];
            float2 fo = *(const float2*)&FOLD[j];
            float f0 = fmaf(klg, q0.w, fo.x);
            float f1 = fmaf(klg, q1.w, fo.y);
            ulonglong2 xy; xy.x = pk2(q0.x, q1.x); xy.y = pk2(q0.y, q1.y);
            ulonglong2 zf; zf.x = pk2(q0.z, q1.z); zf.y = pk2(f0, f1);
            s_xy[t] = xy; s_zf[t] = zf;
        }
        __syncthreads();
#pragma unroll
        for (int it = 0; it < TS / 64; it++) {
            if ((wm >> (tb + it)) & 1ull) continue;
            int p = it * 32 + lane;
            ulonglong2 xy = s_xy[p];
            ulonglong2 zf = s_zf[p];
            u64 a0 = f2fma(rz[0], zf.x, f2fma(ry[0], xy.y, f2fma(rx[0], xy.x, f2add(zf.y, rw[0]))));
            u64 a1 = f2fma(rz[1], zf.x, f2fma(ry[1], xy.y, f2fma(rx[1], xy.x, f2add(zf.y, rw[1]))));
            u64 a2 = f2fma(rz[2], zf.x, f2fma(ry[2], xy.y, f2fma(rx[2], xy.x, f2add(zf.y, rw[2]))));
            u64 a3 = f2fma(rz[3], zf.x, f2fma(ry[3], xy.y, f2fma(rx[3], xy.x, f2add(zf.y, rw[3]))));
            float e0, e1, e2, e3, e4, e5, e6, e7;
            upk2(e0, e1, a0); upk2(e2, e3, a1); upk2(e4, e5, a2); upk2(e6, e7, a3);
            float m0 = fmaxf(fmaxf(e0, e1), fmaxf(e2, e3));
            float m1 = fmaxf(fmaxf(e4, e5), fmaxf(e6, e7));
            if (__all_sync(0xffffffffu, fmaxf(m0, m1) < UF_TH)) continue;
            acc[0] = f2add(acc[0], pk2(ex2f(e0), ex2f(e1)));
            acc[1] = f2add(acc[1], pk2(ex2f(e2), ex2f(e3)));
            acc[2] = f2add(acc[2], pk2(ex2f(e4), ex2f(e5)));
            acc[3] = f2add(acc[3], pk2(ex2f(e6), ex2f(e7)));
        }
        __syncthreads();
    }

#pragma unroll
    for (int off = 16; off; off >>= 1) {
#pragma unroll
        for (int r = 0; r < 4; r++)
            acc[r] = f2add(acc[r], __shfl_down_sync(0xffffffffu, acc[r], off));
    }
    if (lane == 0) {
        int idx4 = (base + r0) >> 2;
        if (MODE == 1) {
            float mx = NEG_INF;
#pragma unroll
            for (int r = 0; r < 4; r++) {
                float lo, hi; upk2(lo, hi, acc[r]);
                float lg = lg2f(rowv[r] / (EMD_EPS + (lo + hi)));
                g_lgL[base + r0 + r] = lg;
                mx = fmaxf(mx, lg);
            }
            g_rmL[idx4] = mx;
        } else {
            float mx2 = NEG_INF, mx3 = NEG_INF;
#pragma unroll
            for (int r = 0; r < 4; r++) {
                float lo, hi; upk2(lo, hi, acc[r]);
                float a = lo + hi;
                float rr   = rowv[r];
                float sumr = rr * a;
                float cons = fminf(rr / (sumr + EMD_EPS), 1.0f);
                float nrr  = fmaxf(0.0f, rr - sumr);
                float lgr  = lg2f(cons * rr);
                float l2r  = lg2f(nrr);
                g_lgR[base + r0 + r] = lgr;
                g_rR[base + r0 + r]  = nrr;
                g_l2R[base + r0 + r] = l2r;
                mx2 = fmaxf(mx2, l2r);
                mx3 = fmaxf(mx3, lgr);
            }
            g_rmR2[idx4] = mx2;
            g_rmR3[idx4] = mx3;
        }
    }
}

// ---------------- standalone P3 (R9 verbatim; used for last sweep) ----------------
__global__ void __launch_bounds__(128, 6) pass3_kernel(float klg, int N) {
    __shared__ ulonglong2 s_xy[TS / 2];
    __shared__ ulonglong2 s_zw[TS / 2];
    __shared__ u64        s_lq[TS / 2];
    __shared__ float s_cm[64];
    __shared__ unsigned s_bm[4][2];
    const int b = blockIdx.y, base = b * N;
    const int t = threadIdx.x, warp = t >> 5, lane = t & 31;
    const int r0 = blockIdx.x * RPB + warp * 4;

    if (t < 64) {
        float m = NEG_INF;
#pragma unroll
        for (int k = 0; k < 16; k++) m = fmaxf(m, g_rmR3[b * (N / 4) + t * 16 + k]);
        s_cm[t] = m;
    }

    u64 rx[4], ry[4], rz[4], rw[4], wa[4], cs[4];
    float lgL[4];
    float4 A[4];
#pragma unroll
    for (int r = 0; r < 4; r++) {
        A[r] = g_p1[base + r0 + r];
        lgL[r] = g_lgL[base + r0 + r];
    }
#pragma unroll
    for (int r = 0; r < 4; r++) {
        rx[r] = pk2(-2.0f * A[r].x, -2.0f * A[r].x);
        ry[r] = pk2(-2.0f * A[r].y, -2.0f * A[r].y);
        rz[r] = pk2(-2.0f * A[r].z, -2.0f * A[r].z);
        rw[r] = pk2(A[r].w, A[r].w);
        wa[r] = 0ull; cs[r] = 0ull;
    }
    float wmaxL = fmaxf(fmaxf(lgL[0], lgL[1]), fmaxf(lgL[2], lgL[3]));
    bool rowsDead = (wmaxL < -126.0f);
    __syncthreads();

    u64 wm;
    if (rowsDead) {
        __ballot_sync(0xffffffffu, 1);
        wm = ~0ull;
        if (lane == 0) { s_bm[warp][0] = 0xffffffffu; s_bm[warp][1] = 0xffffffffu; }
    } else {
        float wlx = fminf(fminf(A[0].x, A[1].x), fminf(A[2].x, A[3].x));
        float whx = fmaxf(fmaxf(A[0].x, A[1].x), fmaxf(A[2].x, A[3].x));
        float wly = fminf(fminf(A[0].y, A[1].y), fminf(A[2].y, A[3].y));
        float why = fmaxf(fmaxf(A[0].y, A[1].y), fmaxf(A[2].y, A[3].y));
        float wlz = fminf(fminf(A[0].z, A[1].z), fminf(A[2].z, A[3].z));
        float whz = fmaxf(fmaxf(A[0].z, A[1].z), fmaxf(A[2].z, A[3].z));
        float g0 = box_gap2(g_cb[1], b * 64 + lane,      wlx, wly, wlz, whx, why, whz);
        float g1 = box_gap2(g_cb[1], b * 64 + lane + 32, wlx, wly, wlz, whx, why, whz);
        bool k0 = fmaf(klg, g0, s_cm[lane]      + wmaxL) < UF_TH;
        bool k1 = fmaf(klg, g1, s_cm[lane + 32] + wmaxL) < UF_TH;
        unsigned lo = __ballot_sync(0xffffffffu, k0);
        unsigned hi = __ballot_sync(0xffffffffu, k1);
        wm = ((u64)hi << 32) | lo;
        if (lane == 0) { s_bm[warp][0] = lo; s_bm[warp][1] = hi; }
    }
    __syncthreads();
    u64 bm = (((u64)(s_bm[0][1] & s_bm[1][1] & s_bm[2][1] & s_bm[3][1])) << 32) |
             (u64)(s_bm[0][0] & s_bm[1][0] & s_bm[2][0] & s_bm[3][0]);
    const u64 klg2 = pk2(klg, klg);

    for (int c = 0; c < N; c += TS) {
        const int tb = c >> 6;
        if (((bm >> tb) & 0xFull) == 0xFull) continue;
        {
            int j = base + c + 2 * t;
            float4 q0 = g_p2[j], q1 = g_p2[j + 1];
            ulonglong2 xy; xy.x = pk2(q0.x, q1.x); xy.y = pk2(q0.y, q1.y);
            ulonglong2 zw; zw.x = pk2(q0.z, q1.z); zw.y = pk2(q0.w, q1.w);
            s_xy[t] = xy; s_zw[t] = zw;
            s_lq[t] = pk2(g_lgR[j], g_lgR[j + 1]);
        }
        __syncthreads();
#pragma unroll
        for (int it = 0; it < TS / 64; it++) {
            if ((wm >> (tb + it)) & 1ull) continue;
            int p = it * 32 + lane;
            ulonglong2 xy = s_xy[p];
            ulonglong2 zw = s_zw[p];
            u64 lq2 = s_lq[p];
            u64 d0 = f2fma(rz[0], zw.x, f2fma(ry[0], xy.y, f2fma(rx[0], xy.x, f2add(zw.y, rw[0]))));
            u64 d1 = f2fma(rz[1], zw.x, f2fma(ry[1], xy.y, f2fma(rx[1], xy.x, f2add(zw.y, rw[1]))));
            u64 d2 = f2fma(rz[2], zw.x, f2fma(ry[2], xy.y, f2fma(rx[2], xy.x, f2add(zw.y, rw[2]))));
            u64 d3 = f2fma(rz[3], zw.x, f2fma(ry[3], xy.y, f2fma(rx[3], xy.x, f2add(zw.y, rw[3]))));
            u64 a0 = f2fma(klg2, d0, lq2);
            u64 a1 = f2fma(klg2, d1, lq2);
            u64 a2 = f2fma(klg2, d2, lq2);
            u64 a3 = f2fma(klg2, d3, lq2);
            float f0, f1, f2v, f3v, f4, f5, f6, f7;
            upk2(f0, f1, a0); upk2(f2v, f3v, a1); upk2(f4, f5, a2); upk2(f6, f7, a3);
            float m0 = fmaxf(fmaxf(f0, f1), fmaxf(f2v, f3v));
            float m1 = fmaxf(fmaxf(f4, f5), fmaxf(f6, f7));
            if (__all_sync(0xffffffffu, fmaxf(m0, m1) < UF_TH)) continue;
#pragma unroll
            for (int r = 0; r < 4; r++) {
                u64 dd = (r == 0) ? d0 : (r == 1) ? d1 : (r == 2) ? d2 : d3;
                float av0, av1;
                if (r == 0)      { av0 = f0;  av1 = f1; }
                else if (r == 1) { av0 = f2v; av1 = f3v; }
                else if (r == 2) { av0 = f4;  av1 = f5; }
                else             { av0 = f6;  av1 = f7; }
                float dl, dh; upk2(dl, dh, dd);
                float c0 = fmaxf(dl, 1e-20f), c1 = fmaxf(dh, 1e-20f);
                float w0 = ex2f(av0), w1 = ex2f(av1);
                float s0 = sqrtf_apx(c0), s1 = sqrtf_apx(c1);
                u64 wv = pk2(w0, w1);
                wa[r] = f2add(wa[r], wv);
                cs[r] = f2fma(wv, pk2(s0, s1), cs[r]);
            }
        }
        __syncthreads();
    }

#pragma unroll
    for (int off = 16; off; off >>= 1) {
#pragma unroll
        for (int r = 0; r < 4; r++) {
            wa[r] = f2add(wa[r], __shfl_down_sync(0xffffffffu, wa[r], off));
            cs[r] = f2add(cs[r], __shfl_down_sync(0xffffffffu, cs[r], off));
        }
    }
    if (lane == 0 && !rowsDead) {
        float cost = 0.0f;
#pragma unroll
        for (int r = 0; r < 4; r++) {
            int idx = base + r0 + r;
            float eL = ex2f(lgL[r]);
            float wl, wh; upk2(wl, wh, wa[r]);
            float cl, ch; upk2(cl, ch, cs[r]);
            g_rL[idx] = fmaxf(0.0f, g_rL[idx] - eL * (wl + wh));
            cost = fmaf(eL, cl + ch, cost);
        }
        atomicAdd(&g_cost, cost);
    }
}

// ---------------- FUSED P3(s) + P1(s+1) ----------------
__global__ void __launch_bounds__(128, 5) fused31_kernel(float klg3, float klg1, int N) {
    __shared__ ulonglong2 s_xy[TS / 2];
    __shared__ ulonglong2 s_zw[TS / 2];
    __shared__ u64        s_lq[TS / 2];   // lgR pairs (P3 fold)
    __shared__ u64        s_fo[TS / 2];   // l2R pairs (P1 fold)
    __shared__ float s_cm3[64];
    __shared__ float s_cm1[64];
    __shared__ unsigned s_bm[4][2];
    const int b = blockIdx.y, base = b * N;
    const int t = threadIdx.x, warp = t >> 5, lane = t & 31;
    const int r0 = blockIdx.x * RPB + warp * 4;

    if (t < 64) {
        float m3 = NEG_INF, m1 = NEG_INF;
#pragma unroll
        for (int k = 0; k < 16; k++) {
            m3 = fmaxf(m3, g_rmR3[b * (N / 4) + t * 16 + k]);
            m1 = fmaxf(m1, g_rmR2[b * (N / 4) + t * 16 + k]);
        }
        s_cm3[t] = m3; s_cm1[t] = m1;
    }

    u64 rx[4], ry[4], rz[4], rw[4], wa[4], cs[4], acc[4];
    float lgL[4], rowv[4];
    float4 A[4];
#pragma unroll
    for (int r = 0; r < 4; r++) {
        A[r] = g_p1[base + r0 + r];
        lgL[r]  = g_lgL[base + r0 + r];
        rowv[r] = g_rL[base + r0 + r];
        rx[r] = pk2(-2.0f * A[r].x, -2.0f * A[r].x);
        ry[r] = pk2(-2.0f * A[r].y, -2.0f * A[r].y);
        rz[r] = pk2(-2.0f * A[r].z, -2.0f * A[r].z);
        rw[r] = pk2(A[r].w, A[r].w);
        wa[r] = 0ull; cs[r] = 0ull; acc[r] = 0ull;
    }
    float wmaxL = fmaxf(fmaxf(lgL[0], lgL[1]), fmaxf(lgL[2], lgL[3]));
    bool dead3 = (wmaxL < -126.0f);
    bool dead1 = (fmaxf(fmaxf(rowv[0], rowv[1]), fmaxf(rowv[2], rowv[3])) == 0.0f);
    __syncthreads();

    u64 wm3, wm1;
    {
        float wlx = fminf(fminf(A[0].x, A[1].x), fminf(A[2].x, A[3].x));
        float whx = fmaxf(fmaxf(A[0].x, A[1].x), fmaxf(A[2].x, A[3].x));
        float wly = fminf(fminf(A[0].y, A[1].y), fminf(A[2].y, A[3].y));
        float why = fmaxf(fmaxf(A[0].y, A[1].y), fmaxf(A[2].y, A[3].y));
        float wlz = fminf(fminf(A[0].z, A[1].z), fminf(A[2].z, A[3].z));
        float whz = fmaxf(fmaxf(A[0].z, A[1].z), fmaxf(A[2].z, A[3].z));
        float g0 = box_gap2(g_cb[1], b * 64 + lane,      wlx, wly, wlz, whx, why, whz);
        float g1 = box_gap2(g_cb[1], b * 64 + lane + 32, wlx, wly, wlz, whx, why, whz);
        bool k30 = dead3 || (fmaf(klg3, g0, s_cm3[lane]      + wmaxL) < UF_TH);
        bool k31 = dead3 || (fmaf(klg3, g1, s_cm3[lane + 32] + wmaxL) < UF_TH);
        bool k10 = dead1 || (fmaf(klg1, g0, s_cm1[lane])      < UF_TH);
        bool k11 = dead1 || (fmaf(klg1, g1, s_cm1[lane + 32]) < UF_TH);
        unsigned lo3 = __ballot_sync(0xffffffffu, k30);
        unsigned hi3 = __ballot_sync(0xffffffffu, k31);
        unsigned lo1 = __ballot_sync(0xffffffffu, k10);
        unsigned hi1 = __ballot_sync(0xffffffffu, k11);
        wm3 = ((u64)hi3 << 32) | lo3;
        wm1 = ((u64)hi1 << 32) | lo1;
        if (lane == 0) { s_bm[warp][0] = lo3 & lo1; s_bm[warp][1] = hi3 & hi1; }
    }
    __syncthreads();
    u64 bm = (((u64)(s_bm[0][1] & s_bm[1][1] & s_bm[2][1] & s_bm[3][1])) << 32) |
             (u64)(s_bm[0][0] & s_bm[1][0] & s_bm[2][0] & s_bm[3][0]);
    const u64 klg3_2 = pk2(klg3, klg3);
    const u64 klg1_2 = pk2(klg1, klg1);

    for (int c = 0; c < N; c += TS) {
        const int tb = c >> 6;
        if (((bm >> tb) & 0xFull) == 0xFull) continue;
        {
            int j = base + c + 2 * t;
            float4 q0 = g_p2[j], q1 = g_p2[j + 1];
            ulonglong2 xy; xy.x = pk2(q0.x, q1.x); xy.y = pk2(q0.y, q1.y);
            ulonglong2 zw; zw.x = pk2(q0.z, q1.z); zw.y = pk2(q0.w, q1.w);
            s_xy[t] = xy; s_zw[t] = zw;
            s_lq[t] = pk2(g_lgR[j], g_lgR[j + 1]);
            s_fo[t] = pk2(g_l2R[j], g_l2R[j + 1]);
        }
        __syncthreads();
#pragma unroll
        for (int it = 0; it < TS / 64; it++) {
            bool skip3 = (wm3 >> (tb + it)) & 1ull;
            bool skip1 = (wm1 >> (tb + it)) & 1ull;
            if (skip3 && skip1) continue;
            int p = it * 32 + lane;
            ulonglong2 xy = s_xy[p];
            ulonglong2 zw = s_zw[p];
            u64 d0 = f2fma(rz[0], zw.x, f2fma(ry[0], xy.y, f2fma(rx[0], xy.x, f2add(zw.y, rw[0]))));
            u64 d1 = f2fma(rz[1], zw.x, f2fma(ry[1], xy.y, f2fma(rx[1], xy.x, f2add(zw.y, rw[1]))));
            u64 d2 = f2fma(rz[2], zw.x, f2fma(ry[2], xy.y, f2fma(rx[2], xy.x, f2add(zw.y, rw[2]))));
            u64 d3 = f2fma(rz[3], zw.x, f2fma(ry[3], xy.y, f2fma(rx[3], xy.x, f2add(zw.y, rw[3]))));
            if (!skip3) {   // P3 side (level s)
                u64 lq2 = s_lq[p];
                u64 a0 = f2fma(klg3_2, d0, lq2);
                u64 a1 = f2fma(klg3_2, d1, lq2);
                u64 a2 = f2fma(klg3_2, d2, lq2);
                u64 a3 = f2fma(klg3_2, d3, lq2);
                float f0, f1, f2v, f3v, f4, f5, f6, f7;
                upk2(f0, f1, a0); upk2(f2v, f3v, a1); upk2(f4, f5, a2); upk2(f6, f7, a3);
                float m0 = fmaxf(fmaxf(f0, f1), fmaxf(f2v, f3v));
                float m1 = fmaxf(fmaxf(f4, f5), fmaxf(f6, f7));
                if (!__all_sync(0xffffffffu, fmaxf(m0, m1) < UF_TH)) {
#pragma unroll
                    for (int r = 0; r < 4; r++) {
                        u64 dd = (r == 0) ? d0 : (r == 1) ? d1 : (r == 2) ? d2 : d3;
                        float av0, av1;
                        if (r == 0)      { av0 = f0;  av1 = f1; }
                        else if (r == 1) { av0 = f2v; av1 = f3v; }
                        else if (r == 2) { av0 = f4;  av1 = f5; }
                        else             { av0 = f6;  av1 = f7; }
                        float dl, dh; upk2(dl, dh, dd);
                        float c0 = fmaxf(dl, 1e-20f), c1 = fmaxf(dh, 1e-20f);
                        float w0 = ex2f(av0), w1 = ex2f(av1);
                        float s0 = sqrtf_apx(c0), s1 = sqrtf_apx(c1);
                        u64 wv = pk2(w0, w1);
                        wa[r] = f2add(wa[r], wv);
                        cs[r] = f2fma(wv, pk2(s0, s1), cs[r]);
                    }
                }
            }
            if (!skip1) {   // P1 side (level s+1)
                u64 fo2 = s_fo[p];
                u64 a0 = f2fma(klg1_2, d0, fo2);
                u64 a1 = f2fma(klg1_2, d1, fo2);
                u64 a2 = f2fma(klg1_2, d2, fo2);
                u64 a3 = f2fma(klg1_2, d3, fo2);
                float e0, e1, e2, e3, e4, e5, e6, e7;
                upk2(e0, e1, a0); upk2(e2, e3, a1); upk2(e4, e5, a2); upk2(e6, e7, a3);
                float m0 = fmaxf(fmaxf(e0, e1), fmaxf(e2, e3));
                float m1 = fmaxf(fmaxf(e4, e5), fmaxf(e6, e7));
                if (!__all_sync(0xffffffffu, fmaxf(m0, m1) < UF_TH)) {
                    acc[0] = f2add(acc[0], pk2(ex2f(e0), ex2f(e1)));
                    acc[1] = f2add(acc[1], pk2(ex2f(e2), ex2f(e3)));
                    acc[2] = f2add(acc[2], pk2(ex2f(e4), ex2f(e5)));
                    acc[3] = f2add(acc[3], pk2(ex2f(e6), ex2f(e7)));
                }
            }
        }
        __syncthreads();
    }

#pragma unroll
    for (int off = 16; off; off >>= 1) {
#pragma unroll
        for (int r = 0; r < 4; r++) {
            wa[r]  = f2add(wa[r],  __shfl_down_sync(0xffffffffu, wa[r],  off));
            cs[r]  = f2add(cs[r],  __shfl_down_sync(0xffffffffu, cs[r],  off));
            acc[r] = f2add(acc[r], __shfl_down_sync(0xffffffffu, acc[r], off));
        }
    }
    if (lane == 0) {
        int idx4 = (base + r0) >> 2;
        float cost = 0.0f;
        float mx = NEG_INF;
#pragma unroll
        for (int r = 0; r < 4; r++) {
            int idx = base + r0 + r;
            float eL = ex2f(lgL[r]);                 // 0 exactly when row dead
            float wl, wh; upk2(wl, wh, wa[r]);
            float cl, ch; upk2(cl, ch, cs[r]);
            float al, ah; upk2(al, ah, acc[r]);
            float rLnew = fmaxf(0.0f, rowv[r] - eL * (wl + wh));
            g_rL[idx] = rLnew;
            cost = fmaf(eL, cl + ch, cost);
            float lg = lg2f(rLnew / (EMD_EPS + (al + ah)));
            g_lgL[idx] = lg;
            mx = fmaxf(mx, lg);
        }
        g_rmL[idx4] = mx;
        if (!dead3) atomicAdd(&g_cost, cost);
    }
}

// ---------------- level == 0 sweep (exact, R9 verbatim) ----------------
__global__ void level0_prep(int N) {
    __shared__ float red[256];
    __shared__ float Tv, Uv;
    const int b = blockIdx.x, base = b * N, t = threadIdx.x;
    float ts = 0.0f, us = 0.0f;
    for (int i = t; i < N; i += 256) { ts += g_rR[base + i]; us += g_rL[base + i]; }
    red[t] = ts; __syncthreads();
    for (int o = 128; o; o >>= 1) { if (t < o) red[t] += red[t + o]; __syncthreads(); }
    if (t == 0) Tv = red[0];
    __syncthreads();
    red[t] = us; __syncthreads();
    for (int o = 128; o; o >>= 1) { if (t < o) red[t] += red[t + o]; __syncthreads(); }
    if (t == 0) Uv = red[0];
    __syncthreads();
    float scale = 1.0f / (EMD_EPS + Tv);
    float S = Uv * scale;
    for (int g = t; g < N / 4; g += 256) {
        float mxR = 0.0f;
#pragma unroll
        for (int k = 0; k < 4; k++) {
            int i = base + g * 4 + k;
            g_lgL[i] = g_rL[i] * scale;
            float rr   = g_rR[i];
            float sumr = rr * S;
            float cons = fminf(rr / (sumr + EMD_EPS), 1.0f);
            float rat  = cons * rr;
            g_lgR[i] = rat;
            mxR = fmaxf(mxR, rat);
        }
        g_rmR3[b * (N / 4) + g] = mxR;
    }
}

__global__ void __launch_bounds__(128, 6) level0_cost(int N) {
    __shared__ ulonglong2 s_xy[TS / 2];
    __shared__ ulonglong2 s_zw[TS / 2];
    __shared__ u64        s_rr[TS / 2];
    __shared__ float s_cm[64];
    __shared__ unsigned s_bm[4][2];
    const int b = blockIdx.y, base = b * N;
    const int t = threadIdx.x, warp = t >> 5, lane = t & 31;
    const int r0 = blockIdx.x * RPB + warp * 4;

    if (t < 64) {
        float m = 0.0f;
#pragma unroll
        for (int k = 0; k < 16; k++) m = fmaxf(m, g_rmR3[b * (N / 4) + t * 16 + k]);
        s_cm[t] = m;
    }

    u64 rx[4], ry[4], rz[4], rw[4], cs[4];
    float rl[4];
#pragma unroll
    for (int r = 0; r < 4; r++) {
        float4 A = g_p1[base + r0 + r];
        rx[r] = pk2(-2.0f * A.x, -2.0f * A.x);
        ry[r] = pk2(-2.0f * A.y, -2.0f * A.y);
        rz[r] = pk2(-2.0f * A.z, -2.0f * A.z);
        rw[r] = pk2(A.w, A.w);
        rl[r] = g_lgL[base + r0 + r];
        cs[r] = 0ull;
    }
    bool rowsDead = (fmaxf(fmaxf(rl[0], rl[1]), fmaxf(rl[2], rl[3])) == 0.0f);
    __syncthreads();

    u64 wm;
    {
        bool k0 = rowsDead || (s_cm[lane]      == 0.0f);
        bool k1 = rowsDead || (s_cm[lane + 32] == 0.0f);
        unsigned lo = __ballot_sync(0xffffffffu, k0);
        unsigned hi = __ballot_sync(0xffffffffu, k1);
        wm = ((u64)hi << 32) | lo;
        if (lane == 0) { s_bm[warp][0] = lo; s_bm[warp][1] = hi; }
    }
    __syncthreads();
    u64 bm = (((u64)(s_bm[0][1] & s_bm[1][1] & s_bm[2][1] & s_bm[3][1])) << 32) |
             (u64)(s_bm[0][0] & s_bm[1][0] & s_bm[2][0] & s_bm[3][0]);

    for (int c = 0; c < N; c += TS) {
        const int tb = c >> 6;
        if (((bm >> tb) & 0xFull) == 0xFull) continue;
        {
            int j = base + c + 2 * t;
            float4 q0 = g_p2[j], q1 = g_p2[j + 1];
            ulonglong2 xy; xy.x = pk2(q0.x, q1.x); xy.y = pk2(q0.y, q1.y);
            ulonglong2 zw; zw.x = pk2(q0.z, q1.z); zw.y = pk2(q0.w, q1.w);
            s_xy[t] = xy; s_zw[t] = zw;
            s_rr[t] = pk2(g_lgR[j], g_lgR[j + 1]);
        }
        __syncthreads();
#pragma unroll
        for (int it = 0; it < TS / 64; it++) {
            if ((wm >> (tb + it)) & 1ull) continue;
            int p = it * 32 + lane;
            ulonglong2 xy = s_xy[p];
            ulonglong2 zw = s_zw[p];
            u64 rr2 = s_rr[p];
            if (__all_sync(0xffffffffu, rr2 == 0ull)) continue;
#pragma unroll
            for (int r = 0; r < 4; r++) {
                u64 dd = f2fma(rz[r], zw.x, f2fma(ry[r], xy.y, f2fma(rx[r], xy.x, f2add(zw.y, rw[r]))));
                float dl, dh; upk2(dl, dh, dd);
                float s0 = sqrtf_apx(fmaxf(dl, 1e-20f));
                float s1 = sqrtf_apx(fmaxf(dh, 1e-20f));
                cs[r] = f2fma(rr2, pk2(s0, s1), cs[r]);
            }
        }
        __syncthreads();
    }

#pragma unroll
    for (int off = 16; off; off >>= 1) {
#pragma unroll
        for (int r = 0; r < 4; r++)
            cs[r] = f2add(cs[r], __shfl_down_sync(0xffffffffu, cs[r], off));
    }
    if (lane == 0 && !rowsDead) {
        float cost = 0.0f;
#pragma unroll
        for (int r = 0; r < 4; r++) {
            float cl, ch; upk2(cl, ch, cs[r]);
            cost = fmaf(rl[r], cl + ch, cost);
        }
        atomicAdd(&g_cost, cost);
    }
}

__global__ void final_kernel(float* out, float inv) {
    out[0] = g_cost * inv;
}

extern "C" void kernel_launch(void* const* d_in, const int* in_sizes, int n_in,
                              void* d_out, int out_size) {
    const float* x1 = (const float*)d_in[0];
    const float* x2 = (const float*)d_in[1];
    const int B = NB;
    const int N = in_sizes[0] / (3 * B);   // 4096
    const int n = N, m = N;

    float multiL, multiR;
    if (n >= m) { multiL = 1.0f; multiR = (float)(n / m); }
    else        { multiL = (float)(m / n); multiR = 1.0f; }

    sort_kernel<<<dim3(B, 2), 512>>>(x1, x2, multiL, multiR, N);
    bbox_kernel<<<dim3(B, 2), 512>>>(N);

    dim3 grid(N / RPB, B);
    const float LOG2E = 1.4426950408889634f;
    auto klg_of = [&](int s) { return -ldexpf(1.0f, 2 * (7 - s)) * LOG2E; };

    pass12_kernel<1><<<grid, 128>>>(klg_of(0), N);   // initial P1 (s0)
    for (int s = 0; s < 9; s++) {
        float klg = klg_of(s);
        pass12_kernel<2><<<grid, 128>>>(klg, N);     // P2 (s)
        if (s < 8) {
            fused31_kernel<<<grid, 128>>>(klg, klg_of(s + 1), N);   // P3(s)+P1(s+1)
        } else {
            pass3_kernel<<<grid, 128>>>(klg, N);     // final P3 (s8)
        }
    }
    level0_prep<<<B, 256>>>(N);
    level0_cost<<<grid, 128>>>(N);

    float mn = (float)((n < m ? n : m) * B);
    final_kernel<<<1, 1>>>((float*)d_out, 1.0f / mn);
}

// round 14
// speedup vs baseline: 1.7618x; 1.0513x over previous
#include <cuda_runtime.h>
#include <math.h>

// EMD approxmatch (Fan et al.) on GB300 — round 14.
// R13 + product-form fused kernel: u = ex2(klg(s+1)*d) serves BOTH passes
// (P1: u*remainR; P3: u^4*ratioR, since klg(s) = 4*klg(s+1) exactly).
// MUFU in fused drops 3->2 lanes/pair. 22 launches. B=4, N=4096.

#define EMD_EPS 1e-9f
#define NB 4
#define MAXBN (NB * 4096)
#define TS 256
#define RPB 16
#define UF_TH (-125.0f)
#define P3_TH (-31.5f)
#define NEG_INF (-__int_as_float(0x7f800000))

typedef unsigned long long u64;

__device__ float4 g_p1[MAXBN];
__device__ float4 g_p2[MAXBN];
__device__ float  g_rL[MAXBN];
__device__ float  g_rR[MAXBN];
__device__ float  g_l2R[MAXBN];    // log2(remainR)
__device__ float  g_lgL[MAXBN];    // log2(ratioL)  (raw ratioL during level-0)
__device__ float  g_lgR[MAXBN];    // log2(ratioR)  (raw ratioR during level-0)
__device__ float  g_ratR[MAXBN];   // raw ratioR (for fused product form)
__device__ float  g_rmL[MAXBN/4];  // per-4-row max lgL (x1)
__device__ float  g_rmR2[MAXBN/4]; // per-4-row max l2R (x2)
__device__ float  g_rmR3[MAXBN/4]; // per-4-row max lgR (x2)
__device__ float  g_cost;
__device__ float4 g_cb[2][NB * 64 * 2];

__device__ __forceinline__ float ex2f(float x) {
    float y; asm("ex2.approx.ftz.f32 %0, %1;" : "=f"(y) : "f"(x)); return y;
}
__device__ __forceinline__ float lg2f(float x) {
    float y; asm("lg2.approx.ftz.f32 %0, %1;" : "=f"(y) : "f"(x)); return y;
}
__device__ __forceinline__ float sqrtf_apx(float x) {
    float y; asm("sqrt.approx.ftz.f32 %0, %1;" : "=f"(y) : "f"(x)); return y;
}
__device__ __forceinline__ u64 pk2(float a, float b) {
    u64 r; asm("mov.b64 %0, {%1, %2};" : "=l"(r) : "f"(a), "f"(b)); return r;
}
__device__ __forceinline__ void upk2(float& a, float& b, u64 v) {
    asm("mov.b64 {%0, %1}, %2;" : "=f"(a), "=f"(b) : "l"(v));
}
__device__ __forceinline__ u64 f2fma(u64 a, u64 b, u64 c) {
    u64 d; asm("fma.rn.f32x2 %0, %1, %2, %3;" : "=l"(d) : "l"(a), "l"(b), "l"(c)); return d;
}
__device__ __forceinline__ u64 f2add(u64 a, u64 b) {
    u64 d; asm("add.rn.f32x2 %0, %1, %2;" : "=l"(d) : "l"(a), "l"(b)); return d;
}
__device__ __forceinline__ u64 f2mul(u64 a, u64 b) {
    u64 d; asm("mul.rn.f32x2 %0, %1, %2;" : "=l"(d) : "l"(a), "l"(b)); return d;
}

__device__ __forceinline__ unsigned mort1(unsigned v) {
    return (v & 1u) | ((v & 2u) << 2) | ((v & 4u) << 4);
}

__device__ __forceinline__ float box_gap2(const float4* CB, int ci,
                                          float wlx, float wly, float wlz,
                                          float whx, float why, float whz) {
    float4 clo = __ldg(&CB[ci * 2]);
    float4 chi = __ldg(&CB[ci * 2 + 1]);
    float gx = fmaxf(0.0f, fmaxf(clo.x - whx, wlx - chi.x));
    float gy = fmaxf(0.0f, fmaxf(clo.y - why, wly - chi.y));
    float gz = fmaxf(0.0f, fmaxf(clo.z - whz, wlz - chi.z));
    return fmaf(gx, gx, fmaf(gy, gy, gz * gz));
}

// Counting sort by Morton cell id. grid (B,2), block 512.
__global__ void sort_kernel(const float* __restrict__ x1, const float* __restrict__ x2,
                            float multiL, float multiR, int N) {
    __shared__ unsigned hist[512];
    __shared__ unsigned scan[512];
    __shared__ unsigned offs[512];
    const int b = blockIdx.x, side = blockIdx.y, t = threadIdx.x;
    const float* px = (side ? x2 : x1) + (size_t)b * 3 * N;
    hist[t] = 0;
    __syncthreads();
    for (int i = t; i < N; i += 512) {
        float a = px[i], c = px[i + N], d = px[i + 2 * N];
        unsigned cx = (unsigned)min(7, max(0, (int)floorf(a + 4.0f)));
        unsigned cy = (unsigned)min(7, max(0, (int)floorf(c + 4.0f)));
        unsigned cz = (unsigned)min(7, max(0, (int)floorf(d + 4.0f)));
        unsigned cell = mort1(cx) | (mort1(cy) << 1) | (mort1(cz) << 2);
        atomicAdd(&hist[cell], 1u);
    }
    __syncthreads();
    scan[t] = hist[t];
    __syncthreads();
    for (int o = 1; o < 512; o <<= 1) {
        unsigned add = (t >= o) ? scan[t - o] : 0u;
        __syncthreads();
        scan[t] += add;
        __syncthreads();
    }
    offs[t] = scan[t] - hist[t];
    __syncthreads();
    for (int i = t; i < N; i += 512) {
        float a = px[i], c = px[i + N], d = px[i + 2 * N];
        unsigned cx = (unsigned)min(7, max(0, (int)floorf(a + 4.0f)));
        unsigned cy = (unsigned)min(7, max(0, (int)floorf(c + 4.0f)));
        unsigned cz = (unsigned)min(7, max(0, (int)floorf(d + 4.0f)));
        unsigned cell = mort1(cx) | (mort1(cy) << 1) | (mort1(cz) << 2);
        unsigned pos = atomicAdd(&offs[cell], 1u);
        int idx = b * N + (int)pos;
        float4 v = make_float4(a, c, d, a * a + c * c + d * d);
        if (side == 0) { g_p1[idx] = v; g_rL[idx] = multiL; }
        else           { g_p2[idx] = v; g_rR[idx] = multiR; g_l2R[idx] = lg2f(multiR); }
    }
    if (side == 1) {
        for (int i = t; i < N / 4; i += 512) g_rmR2[b * (N / 4) + i] = lg2f(multiR);
    }
    if (b == 0 && side == 0 && t == 0) g_cost = 0.0f;
}

// Chunk (64-pt) bboxes. grid (B,2), block 512.
__global__ void bbox_kernel(int N) {
    const int b = blockIdx.x, side = blockIdx.y, t = threadIdx.x;
    const int warp = t >> 5, lane = t & 31;
    const float4* P = side ? g_p2 : g_p1;
    float4* CB = g_cb[side];
    for (int c = warp; c < 64; c += 16) {
        int j = b * N + c * 64 + lane;
        float4 p0 = P[j], p1 = P[j + 32];
        float lx = fminf(p0.x, p1.x), hx = fmaxf(p0.x, p1.x);
        float ly = fminf(p0.y, p1.y), hy = fmaxf(p0.y, p1.y);
        float lz = fminf(p0.z, p1.z), hz = fmaxf(p0.z, p1.z);
#pragma unroll
        for (int o = 16; o; o >>= 1) {
            lx = fminf(lx, __shfl_xor_sync(0xffffffffu, lx, o));
            hx = fmaxf(hx, __shfl_xor_sync(0xffffffffu, hx, o));
            ly = fminf(ly, __shfl_xor_sync(0xffffffffu, ly, o));
            hy = fmaxf(hy, __shfl_xor_sync(0xffffffffu, hy, o));
            lz = fminf(lz, __shfl_xor_sync(0xffffffffu, lz, o));
            hz = fmaxf(hz, __shfl_xor_sync(0xffffffffu, hz, o));
        }
        if (lane == 0) {
            CB[(b * 64 + c) * 2]     = make_float4(lx, ly, lz, 0.0f);
            CB[(b * 64 + c) * 2 + 1] = make_float4(hx, hy, hz, 0.0f);
        }
    }
}

// ---------------- P1/P2 kernel ----------------
template <int MODE>
__global__ void __launch_bounds__(128, 6) pass12_kernel(float klg, int N) {
    __shared__ ulonglong2 s_xy[TS / 2];
    __shared__ ulonglong2 s_zf[TS / 2];
    __shared__ float s_cm[64];
    __shared__ unsigned s_bm[4][2];
    const int b = blockIdx.y, base = b * N;
    const int t = threadIdx.x, warp = t >> 5, lane = t & 31;
    const int r0 = blockIdx.x * RPB + warp * 4;

    const float4* P    = (MODE == 1) ? g_p1 : g_p2;
    const float4* Q    = (MODE == 1) ? g_p2 : g_p1;
    const float4* CB   = (MODE == 1) ? g_cb[1] : g_cb[0];
    const float*  FOLD = (MODE == 1) ? g_l2R : g_lgL;
    const float*  RM   = (MODE == 1) ? g_rmR2 : g_rmL;

    if (t < 64) {
        float m = NEG_INF;
#pragma unroll
        for (int k = 0; k < 16; k++) m = fmaxf(m, RM[b * (N / 4) + t * 16 + k]);
        s_cm[t] = m;
    }

    u64 rx[4], ry[4], rz[4], rw[4], acc[4];
    float4 A[4];
    float rowv[4];
#pragma unroll
    for (int r = 0; r < 4; r++) {
        A[r] = P[base + r0 + r];
        rowv[r] = (MODE == 1) ? g_rL[base + r0 + r] : g_rR[base + r0 + r];
    }
#pragma unroll
    for (int r = 0; r < 4; r++) {
        float kx = klg * -2.0f * A[r].x, ky = klg * -2.0f * A[r].y, kz = klg * -2.0f * A[r].z;
        float kw = klg * A[r].w;
        rx[r] = pk2(kx, kx); ry[r] = pk2(ky, ky); rz[r] = pk2(kz, kz); rw[r] = pk2(kw, kw);
        acc[r] = 0ull;
    }
    bool rowsDead = (fmaxf(fmaxf(rowv[0], rowv[1]), fmaxf(rowv[2], rowv[3])) == 0.0f);
    __syncthreads();

    u64 wm;
    if (rowsDead) {
        __ballot_sync(0xffffffffu, 1);
        wm = ~0ull;
        if (lane == 0) { s_bm[warp][0] = 0xffffffffu; s_bm[warp][1] = 0xffffffffu; }
    } else {
        float wlx = fminf(fminf(A[0].x, A[1].x), fminf(A[2].x, A[3].x));
        float whx = fmaxf(fmaxf(A[0].x, A[1].x), fmaxf(A[2].x, A[3].x));
        float wly = fminf(fminf(A[0].y, A[1].y), fminf(A[2].y, A[3].y));
        float why = fmaxf(fmaxf(A[0].y, A[1].y), fmaxf(A[2].y, A[3].y));
        float wlz = fminf(fminf(A[0].z, A[1].z), fminf(A[2].z, A[3].z));
        float whz = fmaxf(fmaxf(A[0].z, A[1].z), fmaxf(A[2].z, A[3].z));
        float g0 = box_gap2(CB, b * 64 + lane,      wlx, wly, wlz, whx, why, whz);
        float g1 = box_gap2(CB, b * 64 + lane + 32, wlx, wly, wlz, whx, why, whz);
        bool k0 = fmaf(klg, g0, s_cm[lane])      < UF_TH;
        bool k1 = fmaf(klg, g1, s_cm[lane + 32]) < UF_TH;
        unsigned lo = __ballot_sync(0xffffffffu, k0);
        unsigned hi = __ballot_sync(0xffffffffu, k1);
        wm = ((u64)hi << 32) | lo;
        if (lane == 0) { s_bm[warp][0] = lo; s_bm[warp][1] = hi; }
    }
    __syncthreads();
    u64 bm = (((u64)(s_bm[0][1] & s_bm[1][1] & s_bm[2][1] & s_bm[3][1])) << 32) |
             (u64)(s_bm[0][0] & s_bm[1][0] & s_bm[2][0] & s_bm[3][0]);

    for (int c = 0; c < N; c += TS) {
        const int tb = c >> 6;
        if (((bm >> tb) & 0xFull) == 0xFull) continue;
        {
            int j = base + c + 2 * t;
            float4 q0 = Q[j], q1 = Q[j + 1];
            float2 fo = *(const float2*)&FOLD[j];
            float f0 = fmaf(klg, q0.w, fo.x);
            float f1 = fmaf(klg, q1.w, fo.y);
            ulonglong2 xy; xy.x = pk2(q0.x, q1.x); xy.y = pk2(q0.y, q1.y);
            ulonglong2 zf; zf.x = pk2(q0.z, q1.z); zf.y = pk2(f0, f1);
            s_xy[t] = xy; s_zf[t] = zf;
        }
        __syncthreads();
#pragma unroll
        for (int it = 0; it < TS / 64; it++) {
            if ((wm >> (tb + it)) & 1ull) continue;
            int p = it * 32 + lane;
            ulonglong2 xy = s_xy[p];
            ulonglong2 zf = s_zf[p];
            u64 a0 = f2fma(rz[0], zf.x, f2fma(ry[0], xy.y, f2fma(rx[0], xy.x, f2add(zf.y, rw[0]))));
            u64 a1 = f2fma(rz[1], zf.x, f2fma(ry[1], xy.y, f2fma(rx[1], xy.x, f2add(zf.y, rw[1]))));
            u64 a2 = f2fma(rz[2], zf.x, f2fma(ry[2], xy.y, f2fma(rx[2], xy.x, f2add(zf.y, rw[2]))));
            u64 a3 = f2fma(rz[3], zf.x, f2fma(ry[3], xy.y, f2fma(rx[3], xy.x, f2add(zf.y, rw[3]))));
            float e0, e1, e2, e3, e4, e5, e6, e7;
            upk2(e0, e1, a0); upk2(e2, e3, a1); upk2(e4, e5, a2); upk2(e6, e7, a3);
            float m0 = fmaxf(fmaxf(e0, e1), fmaxf(e2, e3));
            float m1 = fmaxf(fmaxf(e4, e5), fmaxf(e6, e7));
            if (__all_sync(0xffffffffu, fmaxf(m0, m1) < UF_TH)) continue;
            acc[0] = f2add(acc[0], pk2(ex2f(e0), ex2f(e1)));
            acc[1] = f2add(acc[1], pk2(ex2f(e2), ex2f(e3)));
            acc[2] = f2add(acc[2], pk2(ex2f(e4), ex2f(e5)));
            acc[3] = f2add(acc[3], pk2(ex2f(e6), ex2f(e7)));
        }
        __syncthreads();
    }

#pragma unroll
    for (int off = 16; off; off >>= 1) {
#pragma unroll
        for (int r = 0; r < 4; r++)
            acc[r] = f2add(acc[r], __shfl_down_sync(0xffffffffu, acc[r], off));
    }
    if (lane == 0) {
        int idx4 = (base + r0) >> 2;
        if (MODE == 1) {
            float mx = NEG_INF;
#pragma unroll
            for (int r = 0; r < 4; r++) {
                float lo, hi; upk2(lo, hi, acc[r]);
                float lg = lg2f(rowv[r] / (EMD_EPS + (lo + hi)));
                g_lgL[base + r0 + r] = lg;
                mx = fmaxf(mx, lg);
            }
            g_rmL[idx4] = mx;
        } else {
            float mx2 = NEG_INF, mx3 = NEG_INF;
#pragma unroll
            for (int r = 0; r < 4; r++) {
                float lo, hi; upk2(lo, hi, acc[r]);
                float a = lo + hi;
                float rr   = rowv[r];
                float sumr = rr * a;
                float cons = fminf(rr / (sumr + EMD_EPS), 1.0f);
                float nrr  = fmaxf(0.0f, rr - sumr);
                float rat  = cons * rr;
                float lgr  = lg2f(rat);
                float l2r  = lg2f(nrr);
                g_lgR[base + r0 + r]  = lgr;
                g_ratR[base + r0 + r] = rat;
                g_rR[base + r0 + r]   = nrr;
                g_l2R[base + r0 + r]  = l2r;
                mx2 = fmaxf(mx2, l2r);
                mx3 = fmaxf(mx3, lgr);
            }
            g_rmR2[idx4] = mx2;
            g_rmR3[idx4] = mx3;
        }
    }
}

// ---------------- standalone P3 (used for last sweep s8) ----------------
__global__ void __launch_bounds__(128, 6) pass3_kernel(float klg, int N) {
    __shared__ ulonglong2 s_xy[TS / 2];
    __shared__ ulonglong2 s_zw[TS / 2];
    __shared__ u64        s_lq[TS / 2];
    __shared__ float s_cm[64];
    __shared__ unsigned s_bm[4][2];
    const int b = blockIdx.y, base = b * N;
    const int t = threadIdx.x, warp = t >> 5, lane = t & 31;
    const int r0 = blockIdx.x * RPB + warp * 4;

    if (t < 64) {
        float m = NEG_INF;
#pragma unroll
        for (int k = 0; k < 16; k++) m = fmaxf(m, g_rmR3[b * (N / 4) + t * 16 + k]);
        s_cm[t] = m;
    }

    u64 rx[4], ry[4], rz[4], rw[4], wa[4], cs[4];
    float lgL[4];
    float4 A[4];
#pragma unroll
    for (int r = 0; r < 4; r++) {
        A[r] = g_p1[base + r0 + r];
        lgL[r] = g_lgL[base + r0 + r];
    }
#pragma unroll
    for (int r = 0; r < 4; r++) {
        rx[r] = pk2(-2.0f * A[r].x, -2.0f * A[r].x);
        ry[r] = pk2(-2.0f * A[r].y, -2.0f * A[r].y);
        rz[r] = pk2(-2.0f * A[r].z, -2.0f * A[r].z);
        rw[r] = pk2(A[r].w, A[r].w);
        wa[r] = 0ull; cs[r] = 0ull;
    }
    float wmaxL = fmaxf(fmaxf(lgL[0], lgL[1]), fmaxf(lgL[2], lgL[3]));
    bool rowsDead = (wmaxL < -126.0f);
    __syncthreads();

    u64 wm;
    if (rowsDead) {
        __ballot_sync(0xffffffffu, 1);
        wm = ~0ull;
        if (lane == 0) { s_bm[warp][0] = 0xffffffffu; s_bm[warp][1] = 0xffffffffu; }
    } else {
        float wlx = fminf(fminf(A[0].x, A[1].x), fminf(A[2].x, A[3].x));
        float whx = fmaxf(fmaxf(A[0].x, A[1].x), fmaxf(A[2].x, A[3].x));
        float wly = fminf(fminf(A[0].y, A[1].y), fminf(A[2].y, A[3].y));
        float why = fmaxf(fmaxf(A[0].y, A[1].y), fmaxf(A[2].y, A[3].y));
        float wlz = fminf(fminf(A[0].z, A[1].z), fminf(A[2].z, A[3].z));
        float whz = fmaxf(fmaxf(A[0].z, A[1].z), fmaxf(A[2].z, A[3].z));
        float g0 = box_gap2(g_cb[1], b * 64 + lane,      wlx, wly, wlz, whx, why, whz);
        float g1 = box_gap2(g_cb[1], b * 64 + lane + 32, wlx, wly, wlz, whx, why, whz);
        bool k0 = fmaf(klg, g0, s_cm[lane]      + wmaxL) < UF_TH;
        bool k1 = fmaf(klg, g1, s_cm[lane + 32] + wmaxL) < UF_TH;
        unsigned lo = __ballot_sync(0xffffffffu, k0);
        unsigned hi = __ballot_sync(0xffffffffu, k1);
        wm = ((u64)hi << 32) | lo;
        if (lane == 0) { s_bm[warp][0] = lo; s_bm[warp][1] = hi; }
    }
    __syncthreads();
    u64 bm = (((u64)(s_bm[0][1] & s_bm[1][1] & s_bm[2][1] & s_bm[3][1])) << 32) |
             (u64)(s_bm[0][0] & s_bm[1][0] & s_bm[2][0] & s_bm[3][0]);
    const u64 klg2 = pk2(klg, klg);

    for (int c = 0; c < N; c += TS) {
        const int tb = c >> 6;
        if (((bm >> tb) & 0xFull) == 0xFull) continue;
        {
            int j = base + c + 2 * t;
            float4 q0 = g_p2[j], q1 = g_p2[j + 1];
            ulonglong2 xy; xy.x = pk2(q0.x, q1.x); xy.y = pk2(q0.y, q1.y);
            ulonglong2 zw; zw.x = pk2(q0.z, q1.z); zw.y = pk2(q0.w, q1.w);
            s_xy[t] = xy; s_zw[t] = zw;
            s_lq[t] = pk2(g_lgR[j], g_lgR[j + 1]);
        }
        __syncthreads();
#pragma unroll
        for (int it = 0; it < TS / 64; it++) {
            if ((wm >> (tb + it)) & 1ull) continue;
            int p = it * 32 + lane;
            ulonglong2 xy = s_xy[p];
            ulonglong2 zw = s_zw[p];
            u64 lq2 = s_lq[p];
            u64 d0 = f2fma(rz[0], zw.x, f2fma(ry[0], xy.y, f2fma(rx[0], xy.x, f2add(zw.y, rw[0]))));
            u64 d1 = f2fma(rz[1], zw.x, f2fma(ry[1], xy.y, f2fma(rx[1], xy.x, f2add(zw.y, rw[1]))));
            u64 d2 = f2fma(rz[2], zw.x, f2fma(ry[2], xy.y, f2fma(rx[2], xy.x, f2add(zw.y, rw[2]))));
            u64 d3 = f2fma(rz[3], zw.x, f2fma(ry[3], xy.y, f2fma(rx[3], xy.x, f2add(zw.y, rw[3]))));
            u64 a0 = f2fma(klg2, d0, lq2);
            u64 a1 = f2fma(klg2, d1, lq2);
            u64 a2 = f2fma(klg2, d2, lq2);
            u64 a3 = f2fma(klg2, d3, lq2);
            float f0, f1, f2v, f3v, f4, f5, f6, f7;
            upk2(f0, f1, a0); upk2(f2v, f3v, a1); upk2(f4, f5, a2); upk2(f6, f7, a3);
            float m0 = fmaxf(fmaxf(f0, f1), fmaxf(f2v, f3v));
            float m1 = fmaxf(fmaxf(f4, f5), fmaxf(f6, f7));
            if (__all_sync(0xffffffffu, fmaxf(m0, m1) < UF_TH)) continue;
#pragma unroll
            for (int r = 0; r < 4; r++) {
                u64 dd = (r == 0) ? d0 : (r == 1) ? d1 : (r == 2) ? d2 : d3;
                float av0, av1;
                if (r == 0)      { av0 = f0;  av1 = f1; }
                else if (r == 1) { av0 = f2v; av1 = f3v; }
                else if (r == 2) { av0 = f4;  av1 = f5; }
                else             { av0 = f6;  av1 = f7; }
                float dl, dh; upk2(dl, dh, dd);
                float c0 = fmaxf(dl, 1e-20f), c1 = fmaxf(dh, 1e-20f);
                float w0 = ex2f(av0), w1 = ex2f(av1);
                float s0 = sqrtf_apx(c0), s1 = sqrtf_apx(c1);
                u64 wv = pk2(w0, w1);
                wa[r] = f2add(wa[r], wv);
                cs[r] = f2fma(wv, pk2(s0, s1), cs[r]);
            }
        }
        __syncthreads();
    }

#pragma unroll
    for (int off = 16; off; off >>= 1) {
#pragma unroll
        for (int r = 0; r < 4; r++) {
            wa[r] = f2add(wa[r], __shfl_down_sync(0xffffffffu, wa[r], off));
            cs[r] = f2add(cs[r], __shfl_down_sync(0xffffffffu, cs[r], off));
        }
    }
    if (lane == 0 && !rowsDead) {
        float cost = 0.0f;
#pragma unroll
        for (int r = 0; r < 4; r++) {
            int idx = base + r0 + r;
            float eL = ex2f(lgL[r]);
            float wl, wh; upk2(wl, wh, wa[r]);
            float cl, ch; upk2(cl, ch, cs[r]);
            g_rL[idx] = fmaxf(0.0f, g_rL[idx] - eL * (wl + wh));
            cost = fmaf(eL, cl + ch, cost);
        }
        atomicAdd(&g_cost, cost);
    }
}

// ---------------- FUSED P3(s) + P1(s+1), product form ----------------
// u = ex2(klg1*d); P1 term = u*remainR_j; P3 term = u^4*ratioR_j (klg3 = 4*klg1).
__global__ void __launch_bounds__(128, 5) fused31_kernel(float klg3, float klg1, int N) {
    __shared__ ulonglong2 s_xy[TS / 2];
    __shared__ ulonglong2 s_zw[TS / 2];
    __shared__ u64        s_rt[TS / 2];   // raw ratioR pairs (P3)
    __shared__ u64        s_rr[TS / 2];   // raw remainR pairs (P1)
    __shared__ float s_cm3[64];
    __shared__ float s_cm1[64];
    __shared__ unsigned s_bm[4][2];
    const int b = blockIdx.y, base = b * N;
    const int t = threadIdx.x, warp = t >> 5, lane = t & 31;
    const int r0 = blockIdx.x * RPB + warp * 4;

    if (t < 64) {
        float m3 = NEG_INF, m1 = NEG_INF;
#pragma unroll
        for (int k = 0; k < 16; k++) {
            m3 = fmaxf(m3, g_rmR3[b * (N / 4) + t * 16 + k]);
            m1 = fmaxf(m1, g_rmR2[b * (N / 4) + t * 16 + k]);
        }
        s_cm3[t] = m3; s_cm1[t] = m1;
    }

    u64 rx[4], ry[4], rz[4], rw[4], wa[4], cs[4], acc[4];
    float lgL[4], rowv[4];
    float4 A[4];
#pragma unroll
    for (int r = 0; r < 4; r++) {
        A[r] = g_p1[base + r0 + r];
        lgL[r]  = g_lgL[base + r0 + r];
        rowv[r] = g_rL[base + r0 + r];
        // pre-scale by klg1 so the FMA chain yields klg1*d directly
        float kx = klg1 * -2.0f * A[r].x, ky = klg1 * -2.0f * A[r].y, kz = klg1 * -2.0f * A[r].z;
        float kw = klg1 * A[r].w;
        rx[r] = pk2(kx, kx); ry[r] = pk2(ky, ky); rz[r] = pk2(kz, kz); rw[r] = pk2(kw, kw);
        wa[r] = 0ull; cs[r] = 0ull; acc[r] = 0ull;
    }
    float wmaxL = fmaxf(fmaxf(lgL[0], lgL[1]), fmaxf(lgL[2], lgL[3]));
    bool dead3 = (wmaxL < -126.0f);
    bool dead1 = (fmaxf(fmaxf(rowv[0], rowv[1]), fmaxf(rowv[2], rowv[3])) == 0.0f);
    __syncthreads();

    u64 wm3, wm1;
    {
        float wlx = fminf(fminf(A[0].x, A[1].x), fminf(A[2].x, A[3].x));
        float whx = fmaxf(fmaxf(A[0].x, A[1].x), fmaxf(A[2].x, A[3].x));
        float wly = fminf(fminf(A[0].y, A[1].y), fminf(A[2].y, A[3].y));
        float why = fmaxf(fmaxf(A[0].y, A[1].y), fmaxf(A[2].y, A[3].y));
        float wlz = fminf(fminf(A[0].z, A[1].z), fminf(A[2].z, A[3].z));
        float whz = fmaxf(fmaxf(A[0].z, A[1].z), fmaxf(A[2].z, A[3].z));
        float g0 = box_gap2(g_cb[1], b * 64 + lane,      wlx, wly, wlz, whx, why, whz);
        float g1 = box_gap2(g_cb[1], b * 64 + lane + 32, wlx, wly, wlz, whx, why, whz);
        bool k30 = dead3 || (fmaf(klg3, g0, s_cm3[lane]      + wmaxL) < UF_TH);
        bool k31 = dead3 || (fmaf(klg3, g1, s_cm3[lane + 32] + wmaxL) < UF_TH);
        bool k10 = dead1 || (fmaf(klg1, g0, s_cm1[lane])      < UF_TH);
        bool k11 = dead1 || (fmaf(klg1, g1, s_cm1[lane + 32]) < UF_TH);
        unsigned lo3 = __ballot_sync(0xffffffffu, k30);
        unsigned hi3 = __ballot_sync(0xffffffffu, k31);
        unsigned lo1 = __ballot_sync(0xffffffffu, k10);
        unsigned hi1 = __ballot_sync(0xffffffffu, k11);
        wm3 = ((u64)hi3 << 32) | lo3;
        wm1 = ((u64)hi1 << 32) | lo1;
        if (lane == 0) { s_bm[warp][0] = lo3 & lo1; s_bm[warp][1] = hi3 & hi1; }
    }
    __syncthreads();
    u64 bm = (((u64)(s_bm[0][1] & s_bm[1][1] & s_bm[2][1] & s_bm[3][1])) << 32) |
             (u64)(s_bm[0][0] & s_bm[1][0] & s_bm[2][0] & s_bm[3][0]);
    const float inv_klg1 = 1.0f / klg1;
    const u64 inv2 = pk2(inv_klg1, inv_klg1);

    for (int c = 0; c < N; c += TS) {
        const int tb = c >> 6;
        if (((bm >> tb) & 0xFull) == 0xFull) continue;
        {
            int j = base + c + 2 * t;
            float4 q0 = g_p2[j], q1 = g_p2[j + 1];
            ulonglong2 xy; xy.x = pk2(q0.x, q1.x); xy.y = pk2(q0.y, q1.y);
            ulonglong2 zw; zw.x = pk2(q0.z, q1.z); zw.y = pk2(klg1 * q0.w, klg1 * q1.w);
            s_xy[t] = xy; s_zw[t] = zw;
            s_rt[t] = pk2(g_ratR[j], g_ratR[j + 1]);
            s_rr[t] = pk2(g_rR[j],   g_rR[j + 1]);
        }
        __syncthreads();
#pragma unroll
        for (int it = 0; it < TS / 64; it++) {
            bool skip3 = (wm3 >> (tb + it)) & 1ull;
            bool skip1 = (wm1 >> (tb + it)) & 1ull;
            if (skip3 && skip1) continue;
            int p = it * 32 + lane;
            ulonglong2 xy = s_xy[p];
            ulonglong2 zw = s_zw[p];
            // a = klg1 * d (row constants pre-scaled, column w pre-scaled)
            u64 a0 = f2fma(rz[0], zw.x, f2fma(ry[0], xy.y, f2fma(rx[0], xy.x, f2add(zw.y, rw[0]))));
            u64 a1 = f2fma(rz[1], zw.x, f2fma(ry[1], xy.y, f2fma(rx[1], xy.x, f2add(zw.y, rw[1]))));
            u64 a2 = f2fma(rz[2], zw.x, f2fma(ry[2], xy.y, f2fma(rx[2], xy.x, f2add(zw.y, rw[2]))));
            u64 a3 = f2fma(rz[3], zw.x, f2fma(ry[3], xy.y, f2fma(rx[3], xy.x, f2add(zw.y, rw[3]))));
            float e0, e1, e2, e3, e4, e5, e6, e7;
            upk2(e0, e1, a0); upk2(e2, e3, a1); upk2(e4, e5, a2); upk2(e6, e7, a3);
            float mx = fmaxf(fmaxf(fmaxf(e0, e1), fmaxf(e2, e3)),
                             fmaxf(fmaxf(e4, e5), fmaxf(e6, e7)));
            if (__all_sync(0xffffffffu, mx < UF_TH)) continue;   // u == 0 everywhere
            u64 u0 = pk2(ex2f(e0), ex2f(e1));
            u64 u1 = pk2(ex2f(e2), ex2f(e3));
            u64 u2 = pk2(ex2f(e4), ex2f(e5));
            u64 u3 = pk2(ex2f(e6), ex2f(e7));
            if (!skip1) {   // P1(s+1): suml += u * remainR
                u64 rr2 = s_rr[p];
                acc[0] = f2fma(u0, rr2, acc[0]);
                acc[1] = f2fma(u1, rr2, acc[1]);
                acc[2] = f2fma(u2, rr2, acc[2]);
                acc[3] = f2fma(u3, rr2, acc[3]);
            }
            // P3(s): w = u^4 * ratioR; skip if u^4 provably ftz for all lanes
            if (!skip3 && !__all_sync(0xffffffffu, mx < P3_TH)) {
                u64 rt2 = s_rt[p];
#pragma unroll
                for (int r = 0; r < 4; r++) {
                    u64 uu = (r == 0) ? u0 : (r == 1) ? u1 : (r == 2) ? u2 : u3;
                    u64 aa = (r == 0) ? a0 : (r == 1) ? a1 : (r == 2) ? a2 : a3;
                    u64 sq = f2mul(uu, uu);
                    u64 qd = f2mul(sq, sq);          // u^4 = ex2(klg3*d)
                    u64 wv = f2mul(qd, rt2);
                    wa[r] = f2add(wa[r], wv);
                    // recover d = a / klg1 for sqrt
                    float al, ah; upk2(al, ah, aa);
                    float dl = al * inv_klg1, dh = ah * inv_klg1;
                    float s0 = sqrtf_apx(fmaxf(dl, 1e-20f));
                    float s1 = sqrtf_apx(fmaxf(dh, 1e-20f));
                    cs[r] = f2fma(wv, pk2(s0, s1), cs[r]);
                }
            }
        }
        __syncthreads();
    }

#pragma unroll
    for (int off = 16; off; off >>= 1) {
#pragma unroll
        for (int r = 0; r < 4; r++) {
            wa[r]  = f2add(wa[r],  __shfl_down_sync(0xffffffffu, wa[r],  off));
            cs[r]  = f2add(cs[r],  __shfl_down_sync(0xffffffffu, cs[r],  off));
            acc[r] = f2add(acc[r], __shfl_down_sync(0xffffffffu, acc[r], off));
        }
    }
    if (lane == 0) {
        int idx4 = (base + r0) >> 2;
        float cost = 0.0f;
        float mx = NEG_INF;
#pragma unroll
        for (int r = 0; r < 4; r++) {
            int idx = base + r0 + r;
            float eL = ex2f(lgL[r]);
            float wl, wh; upk2(wl, wh, wa[r]);
            float cl, ch; upk2(cl, ch, cs[r]);
            float al, ah; upk2(al, ah, acc[r]);
            float rLnew = fmaxf(0.0f, rowv[r] - eL * (wl + wh));
            g_rL[idx] = rLnew;
            cost = fmaf(eL, cl + ch, cost);
            float lg = lg2f(rLnew / (EMD_EPS + (al + ah)));
            g_lgL[idx] = lg;
            mx = fmaxf(mx, lg);
        }
        g_rmL[idx4] = mx;
        if (!dead3) atomicAdd(&g_cost, cost);
    }
}

// ---------------- level == 0 sweep (exact) ----------------
__global__ void level0_prep(int N) {
    __shared__ float red[256];
    __shared__ float Tv, Uv;
    const int b = blockIdx.x, base = b * N, t = threadIdx.x;
    float ts = 0.0f, us = 0.0f;
    for (int i = t; i < N; i += 256) { ts += g_rR[base + i]; us += g_rL[base + i]; }
    red[t] = ts; __syncthreads();
    for (int o = 128; o; o >>= 1) { if (t < o) red[t] += red[t + o]; __syncthreads(); }
    if (t == 0) Tv = red[0];
    __syncthreads();
    red[t] = us; __syncthreads();
    for (int o = 128; o; o >>= 1) { if (t < o) red[t] += red[t + o]; __syncthreads(); }
    if (t == 0) Uv = red[0];
    __syncthreads();
    float scale = 1.0f / (EMD_EPS + Tv);
    float S = Uv * scale;
    for (int g = t; g < N / 4; g += 256) {
        float mxR = 0.0f;
#pragma unroll
        for (int k = 0; k < 4; k++) {
            int i = base + g * 4 + k;
            g_lgL[i] = g_rL[i] * scale;
            float rr   = g_rR[i];
            float sumr = rr * S;
            float cons = fminf(rr / (sumr + EMD_EPS), 1.0f);
            float rat  = cons * rr;
            g_lgR[i] = rat;
            mxR = fmaxf(mxR, rat);
        }
        g_rmR3[b * (N / 4) + g] = mxR;
    }
}

__global__ void __launch_bounds__(128, 6) level0_cost(int N) {
    __shared__ ulonglong2 s_xy[TS / 2];
    __shared__ ulonglong2 s_zw[TS / 2];
    __shared__ u64        s_rr[TS / 2];
    __shared__ float s_cm[64];
    __shared__ unsigned s_bm[4][2];
    const int b = blockIdx.y, base = b * N;
    const int t = threadIdx.x, warp = t >> 5, lane = t & 31;
    const int r0 = blockIdx.x * RPB + warp * 4;

    if (t < 64) {
        float m = 0.0f;
#pragma unroll
        for (int k = 0; k < 16; k++) m = fmaxf(m, g_rmR3[b * (N / 4) + t * 16 + k]);
        s_cm[t] = m;
    }

    u64 rx[4], ry[4], rz[4], rw[4], cs[4];
    float rl[4];
#pragma unroll
    for (int r = 0; r < 4; r++) {
        float4 A = g_p1[base + r0 + r];
        rx[r] = pk2(-2.0f * A.x, -2.0f * A.x);
        ry[r] = pk2(-2.0f * A.y, -2.0f * A.y);
        rz[r] = pk2(-2.0f * A.z, -2.0f * A.z);
        rw[r] = pk2(A.w, A.w);
        rl[r] = g_lgL[base + r0 + r];
        cs[r] = 0ull;
    }
    bool rowsDead = (fmaxf(fmaxf(rl[0], rl[1]), fmaxf(rl[2], rl[3])) == 0.0f);
    __syncthreads();

    u64 wm;
    {
        bool k0 = rowsDead || (s_cm[lane]      == 0.0f);
        bool k1 = rowsDead || (s_cm[lane + 32] == 0.0f);
        unsigned lo = __ballot_sync(0xffffffffu, k0);
        unsigned hi = __ballot_sync(0xffffffffu, k1);
        wm = ((u64)hi << 32) | lo;
        if (lane == 0) { s_bm[warp][0] = lo; s_bm[warp][1] = hi; }
    }
    __syncthreads();
    u64 bm = (((u64)(s_bm[0][1] & s_bm[1][1] & s_bm[2][1] & s_bm[3][1])) << 32) |
             (u64)(s_bm[0][0] & s_bm[1][0] & s_bm[2][0] & s_bm[3][0]);

    for (int c = 0; c < N; c += TS) {
        const int tb = c >> 6;
        if (((bm >> tb) & 0xFull) == 0xFull) continue;
        {
            int j = base + c + 2 * t;
            float4 q0 = g_p2[j], q1 = g_p2[j + 1];
            ulonglong2 xy; xy.x = pk2(q0.x, q1.x); xy.y = pk2(q0.y, q1.y);
            ulonglong2 zw; zw.x = pk2(q0.z, q1.z); zw.y = pk2(q0.w, q1.w);
            s_xy[t] = xy; s_zw[t] = zw;
            s_rr[t] = pk2(g_lgR[j], g_lgR[j + 1]);
        }
        __syncthreads();
#pragma unroll
        for (int it = 0; it < TS / 64; it++) {
            if ((wm >> (tb + it)) & 1ull) continue;
            int p = it * 32 + lane;
            ulonglong2 xy = s_xy[p];
            ulonglong2 zw = s_zw[p];
            u64 rr2 = s_rr[p];
            if (__all_sync(0xffffffffu, rr2 == 0ull)) continue;
#pragma unroll
            for (int r = 0; r < 4; r++) {
                u64 dd = f2fma(rz[r], zw.x, f2fma(ry[r], xy.y, f2fma(rx[r], xy.x, f2add(zw.y, rw[r]))));
                float dl, dh; upk2(dl, dh, dd);
                float s0 = sqrtf_apx(fmaxf(dl, 1e-20f));
                float s1 = sqrtf_apx(fmaxf(dh, 1e-20f));
                cs[r] = f2fma(rr2, pk2(s0, s1), cs[r]);
            }
        }
        __syncthreads();
    }

#pragma unroll
    for (int off = 16; off; off >>= 1) {
#pragma unroll
        for (int r = 0; r < 4; r++)
            cs[r] = f2add(cs[r], __shfl_down_sync(0xffffffffu, cs[r], off));
    }
    if (lane == 0 && !rowsDead) {
        float cost = 0.0f;
#pragma unroll
        for (int r = 0; r < 4; r++) {
            float cl, ch; upk2(cl, ch, cs[r]);
            cost = fmaf(rl[r], cl + ch, cost);
        }
        atomicAdd(&g_cost, cost);
    }
}

__global__ void final_kernel(float* out, float inv) {
    out[0] = g_cost * inv;
}

extern "C" void kernel_launch(void* const* d_in, const int* in_sizes, int n_in,
                              void* d_out, int out_size) {
    const float* x1 = (const float*)d_in[0];
    const float* x2 = (const float*)d_in[1];
    const int B = NB;
    const int N = in_sizes[0] / (3 * B);   // 4096
    const int n = N, m = N;

    float multiL, multiR;
    if (n >= m) { multiL = 1.0f; multiR = (float)(n / m); }
    else        { multiL = (float)(m / n); multiR = 1.0f; }

    sort_kernel<<<dim3(B, 2), 512>>>(x1, x2, multiL, multiR, N);
    bbox_kernel<<<dim3(B, 2), 512>>>(N);

    dim3 grid(N / RPB, B);
    const float LOG2E = 1.4426950408889634f;
    auto klg_of = [&](int s) { return -ldexpf(1.0f, 2 * (7 - s)) * LOG2E; };

    pass12_kernel<1><<<grid, 128>>>(klg_of(0), N);   // initial P1 (s0)
    for (int s = 0; s < 9; s++) {
        float klg = klg_of(s);
        pass12_kernel<2><<<grid, 128>>>(klg, N);     // P2 (s)
        if (s < 8) {
            fused31_kernel<<<grid, 128>>>(klg, klg_of(s + 1), N);   // P3(s)+P1(s+1)
        } else {
            pass3_kernel<<<grid, 128>>>(klg, N);     // final P3 (s8)
        }
    }
    level0_prep<<<B, 256>>>(N);
    level0_cost<<<grid, 128>>>(N);

    float mn = (float)((n < m ? n : m) * B);
    final_kernel<<<1, 1>>>((float*)d_out, 1.0f / mn);
}

// round 16
// speedup vs baseline: 1.7842x; 1.0127x over previous
#include <cuda_runtime.h>
#include <math.h>

// EMD approxmatch (Fan et al.) on GB300 — round 16.
// R15 with per-batch level-0 accumulators (fix): G_i reuses P3(s8)'s sqrt;
// per-batch closed-form level-0 cost = scale_b*kappa_b*sum_i rL_i*G_i.
// 20 launches. B=4, N=4096.

#define EMD_EPS 1e-9f
#define NB 4
#define MAXBN (NB * 4096)
#define TS 256
#define RPB 16
#define UF_TH (-125.0f)
#define P3_TH (-31.5f)
#define NEG_INF (-__int_as_float(0x7f800000))

typedef unsigned long long u64;

__device__ float4 g_p1[MAXBN];
__device__ float4 g_p2[MAXBN];
__device__ float  g_rL[MAXBN];
__device__ float  g_rR[MAXBN];
__device__ float  g_l2R[MAXBN];    // log2(remainR)
__device__ float  g_lgL[MAXBN];    // log2(ratioL)
__device__ float  g_lgR[MAXBN];    // log2(ratioR)
__device__ float  g_ratR[MAXBN];   // raw ratioR (fused product form)
__device__ float  g_rmL[MAXBN/4];  // per-4-row max lgL (x1)
__device__ float  g_rmR2[MAXBN/4]; // per-4-row max l2R (x2)
__device__ float  g_rmR3[MAXBN/4]; // per-4-row max lgR (x2)
__device__ float  g_rmNR[MAXBN/4]; // per-4-row max remainR (x2)
__device__ float  g_cost;
__device__ float  g_sumT[NB];      // per-batch sum remainR post P2(s8)
__device__ float  g_sumL[NB];      // per-batch sum remainL post P3(s8)
__device__ float  g_sumLG[NB];     // per-batch sum remainL_i * G_i
__device__ float4 g_cb[2][NB * 64 * 2];

__device__ __forceinline__ float ex2f(float x) {
    float y; asm("ex2.approx.ftz.f32 %0, %1;" : "=f"(y) : "f"(x)); return y;
}
__device__ __forceinline__ float lg2f(float x) {
    float y; asm("lg2.approx.ftz.f32 %0, %1;" : "=f"(y) : "f"(x)); return y;
}
__device__ __forceinline__ float sqrtf_apx(float x) {
    float y; asm("sqrt.approx.ftz.f32 %0, %1;" : "=f"(y) : "f"(x)); return y;
}
__device__ __forceinline__ u64 pk2(float a, float b) {
    u64 r; asm("mov.b64 %0, {%1, %2};" : "=l"(r) : "f"(a), "f"(b)); return r;
}
__device__ __forceinline__ void upk2(float& a, float& b, u64 v) {
    asm("mov.b64 {%0, %1}, %2;" : "=f"(a), "=f"(b) : "l"(v));
}
__device__ __forceinline__ u64 f2fma(u64 a, u64 b, u64 c) {
    u64 d; asm("fma.rn.f32x2 %0, %1, %2, %3;" : "=l"(d) : "l"(a), "l"(b), "l"(c)); return d;
}
__device__ __forceinline__ u64 f2add(u64 a, u64 b) {
    u64 d; asm("add.rn.f32x2 %0, %1, %2;" : "=l"(d) : "l"(a), "l"(b)); return d;
}
__device__ __forceinline__ u64 f2mul(u64 a, u64 b) {
    u64 d; asm("mul.rn.f32x2 %0, %1, %2;" : "=l"(d) : "l"(a), "l"(b)); return d;
}

__device__ __forceinline__ unsigned mort1(unsigned v) {
    return (v & 1u) | ((v & 2u) << 2) | ((v & 4u) << 4);
}

__device__ __forceinline__ float box_gap2(const float4* CB, int ci,
                                          float wlx, float wly, float wlz,
                                          float whx, float why, float whz) {
    float4 clo = __ldg(&CB[ci * 2]);
    float4 chi = __ldg(&CB[ci * 2 + 1]);
    float gx = fmaxf(0.0f, fmaxf(clo.x - whx, wlx - chi.x));
    float gy = fmaxf(0.0f, fmaxf(clo.y - why, wly - chi.y));
    float gz = fmaxf(0.0f, fmaxf(clo.z - whz, wlz - chi.z));
    return fmaf(gx, gx, fmaf(gy, gy, gz * gz));
}

// Counting sort by Morton cell id + chunk bboxes. grid (B,2), block 512.
__global__ void sort_kernel(const float* __restrict__ x1, const float* __restrict__ x2,
                            float multiL, float multiR, int N) {
    __shared__ unsigned hist[512];
    __shared__ unsigned scan[512];
    __shared__ unsigned offs[512];
    const int b = blockIdx.x, side = blockIdx.y, t = threadIdx.x;
    const int warp = t >> 5, lane = t & 31;
    const float* px = (side ? x2 : x1) + (size_t)b * 3 * N;
    hist[t] = 0;
    __syncthreads();
    for (int i = t; i < N; i += 512) {
        float a = px[i], c = px[i + N], d = px[i + 2 * N];
        unsigned cx = (unsigned)min(7, max(0, (int)floorf(a + 4.0f)));
        unsigned cy = (unsigned)min(7, max(0, (int)floorf(c + 4.0f)));
        unsigned cz = (unsigned)min(7, max(0, (int)floorf(d + 4.0f)));
        unsigned cell = mort1(cx) | (mort1(cy) << 1) | (mort1(cz) << 2);
        atomicAdd(&hist[cell], 1u);
    }
    __syncthreads();
    scan[t] = hist[t];
    __syncthreads();
    for (int o = 1; o < 512; o <<= 1) {
        unsigned add = (t >= o) ? scan[t - o] : 0u;
        __syncthreads();
        scan[t] += add;
        __syncthreads();
    }
    offs[t] = scan[t] - hist[t];
    __syncthreads();
    for (int i = t; i < N; i += 512) {
        float a = px[i], c = px[i + N], d = px[i + 2 * N];
        unsigned cx = (unsigned)min(7, max(0, (int)floorf(a + 4.0f)));
        unsigned cy = (unsigned)min(7, max(0, (int)floorf(c + 4.0f)));
        unsigned cz = (unsigned)min(7, max(0, (int)floorf(d + 4.0f)));
        unsigned cell = mort1(cx) | (mort1(cy) << 1) | (mort1(cz) << 2);
        unsigned pos = atomicAdd(&offs[cell], 1u);
        int idx = b * N + (int)pos;
        float4 v = make_float4(a, c, d, a * a + c * c + d * d);
        if (side == 0) { g_p1[idx] = v; g_rL[idx] = multiL; }
        else           { g_p2[idx] = v; g_rR[idx] = multiR; g_l2R[idx] = lg2f(multiR); }
    }
    if (side == 1) {
        for (int i = t; i < N / 4; i += 512) g_rmR2[b * (N / 4) + i] = lg2f(multiR);
    }
    if (side == 0 && t == 0) {
        if (b == 0) g_cost = 0.0f;
        g_sumT[b] = 0.0f; g_sumL[b] = 0.0f; g_sumLG[b] = 0.0f;
    }
    __syncthreads();
    const float4* P = side ? g_p2 : g_p1;
    float4* CB = g_cb[side];
    for (int c = warp; c < 64; c += 16) {
        int j = b * N + c * 64 + lane;
        float4 p0 = P[j], p1 = P[j + 32];
        float lx = fminf(p0.x, p1.x), hx = fmaxf(p0.x, p1.x);
        float ly = fminf(p0.y, p1.y), hy = fmaxf(p0.y, p1.y);
        float lz = fminf(p0.z, p1.z), hz = fmaxf(p0.z, p1.z);
#pragma unroll
        for (int o = 16; o; o >>= 1) {
            lx = fminf(lx, __shfl_xor_sync(0xffffffffu, lx, o));
            hx = fmaxf(hx, __shfl_xor_sync(0xffffffffu, hx, o));
            ly = fminf(ly, __shfl_xor_sync(0xffffffffu, ly, o));
            hy = fmaxf(hy, __shfl_xor_sync(0xffffffffu, hy, o));
            lz = fminf(lz, __shfl_xor_sync(0xffffffffu, lz, o));
            hz = fmaxf(hz, __shfl_xor_sync(0xffffffffu, hz, o));
        }
        if (lane == 0) {
            CB[(b * 64 + c) * 2]     = make_float4(lx, ly, lz, 0.0f);
            CB[(b * 64 + c) * 2 + 1] = make_float4(hx, hy, hz, 0.0f);
        }
    }
}

// ---------------- P1/P2 kernel ----------------
template <int MODE>
__global__ void __launch_bounds__(128, 6) pass12_kernel(float klg, int N, int accT) {
    __shared__ ulonglong2 s_xy[TS / 2];
    __shared__ ulonglong2 s_zf[TS / 2];
    __shared__ float s_cm[64];
    __shared__ unsigned s_bm[4][2];
    const int b = blockIdx.y, base = b * N;
    const int t = threadIdx.x, warp = t >> 5, lane = t & 31;
    const int r0 = blockIdx.x * RPB + warp * 4;

    const float4* P    = (MODE == 1) ? g_p1 : g_p2;
    const float4* Q    = (MODE == 1) ? g_p2 : g_p1;
    const float4* CB   = (MODE == 1) ? g_cb[1] : g_cb[0];
    const float*  FOLD = (MODE == 1) ? g_l2R : g_lgL;
    const float*  RM   = (MODE == 1) ? g_rmR2 : g_rmL;

    if (t < 64) {
        float m = NEG_INF;
#pragma unroll
        for (int k = 0; k < 16; k++) m = fmaxf(m, RM[b * (N / 4) + t * 16 + k]);
        s_cm[t] = m;
    }

    u64 rx[4], ry[4], rz[4], rw[4], acc[4];
    float4 A[4];
    float rowv[4];
#pragma unroll
    for (int r = 0; r < 4; r++) {
        A[r] = P[base + r0 + r];
        rowv[r] = (MODE == 1) ? g_rL[base + r0 + r] : g_rR[base + r0 + r];
    }
#pragma unroll
    for (int r = 0; r < 4; r++) {
        float kx = klg * -2.0f * A[r].x, ky = klg * -2.0f * A[r].y, kz = klg * -2.0f * A[r].z;
        float kw = klg * A[r].w;
        rx[r] = pk2(kx, kx); ry[r] = pk2(ky, ky); rz[r] = pk2(kz, kz); rw[r] = pk2(kw, kw);
        acc[r] = 0ull;
    }
    bool rowsDead = (fmaxf(fmaxf(rowv[0], rowv[1]), fmaxf(rowv[2], rowv[3])) == 0.0f);
    __syncthreads();

    u64 wm;
    if (rowsDead) {
        __ballot_sync(0xffffffffu, 1);
        wm = ~0ull;
        if (lane == 0) { s_bm[warp][0] = 0xffffffffu; s_bm[warp][1] = 0xffffffffu; }
    } else {
        float wlx = fminf(fminf(A[0].x, A[1].x), fminf(A[2].x, A[3].x));
        float whx = fmaxf(fmaxf(A[0].x, A[1].x), fmaxf(A[2].x, A[3].x));
        float wly = fminf(fminf(A[0].y, A[1].y), fminf(A[2].y, A[3].y));
        float why = fmaxf(fmaxf(A[0].y, A[1].y), fmaxf(A[2].y, A[3].y));
        float wlz = fminf(fminf(A[0].z, A[1].z), fminf(A[2].z, A[3].z));
        float whz = fmaxf(fmaxf(A[0].z, A[1].z), fmaxf(A[2].z, A[3].z));
        float g0 = box_gap2(CB, b * 64 + lane,      wlx, wly, wlz, whx, why, whz);
        float g1 = box_gap2(CB, b * 64 + lane + 32, wlx, wly, wlz, whx, why, whz);
        bool k0 = fmaf(klg, g0, s_cm[lane])      < UF_TH;
        bool k1 = fmaf(klg, g1, s_cm[lane + 32]) < UF_TH;
        unsigned lo = __ballot_sync(0xffffffffu, k0);
        unsigned hi = __ballot_sync(0xffffffffu, k1);
        wm = ((u64)hi << 32) | lo;
        if (lane == 0) { s_bm[warp][0] = lo; s_bm[warp][1] = hi; }
    }
    __syncthreads();
    u64 bm = (((u64)(s_bm[0][1] & s_bm[1][1] & s_bm[2][1] & s_bm[3][1])) << 32) |
             (u64)(s_bm[0][0] & s_bm[1][0] & s_bm[2][0] & s_bm[3][0]);

    for (int c = 0; c < N; c += TS) {
        const int tb = c >> 6;
        if (((bm >> tb) & 0xFull) == 0xFull) continue;
        {
            int j = base + c + 2 * t;
            float4 q0 = Q[j], q1 = Q[j + 1];
            float2 fo = *(const float2*)&FOLD[j];
            float f0 = fmaf(klg, q0.w, fo.x);
            float f1 = fmaf(klg, q1.w, fo.y);
            ulonglong2 xy; xy.x = pk2(q0.x, q1.x); xy.y = pk2(q0.y, q1.y);
            ulonglong2 zf; zf.x = pk2(q0.z, q1.z); zf.y = pk2(f0, f1);
            s_xy[t] = xy; s_zf[t] = zf;
        }
        __syncthreads();
#pragma unroll
        for (int it = 0; it < TS / 64; it++) {
            if ((wm >> (tb + it)) & 1ull) continue;
            int p = it * 32 + lane;
            ulonglong2 xy = s_xy[p];
            ulonglong2 zf = s_zf[p];
            u64 a0 = f2fma(rz[0], zf.x, f2fma(ry[0], xy.y, f2fma(rx[0], xy.x, f2add(zf.y, rw[0]))));
            u64 a1 = f2fma(rz[1], zf.x, f2fma(ry[1], xy.y, f2fma(rx[1], xy.x, f2add(zf.y, rw[1]))));
            u64 a2 = f2fma(rz[2], zf.x, f2fma(ry[2], xy.y, f2fma(rx[2], xy.x, f2add(zf.y, rw[2]))));
            u64 a3 = f2fma(rz[3], zf.x, f2fma(ry[3], xy.y, f2fma(rx[3], xy.x, f2add(zf.y, rw[3]))));
            float e0, e1, e2, e3, e4, e5, e6, e7;
            upk2(e0, e1, a0); upk2(e2, e3, a1); upk2(e4, e5, a2); upk2(e6, e7, a3);
            float m0 = fmaxf(fmaxf(e0, e1), fmaxf(e2, e3));
            float m1 = fmaxf(fmaxf(e4, e5), fmaxf(e6, e7));
            if (__all_sync(0xffffffffu, fmaxf(m0, m1) < UF_TH)) continue;
            acc[0] = f2add(acc[0], pk2(ex2f(e0), ex2f(e1)));
            acc[1] = f2add(acc[1], pk2(ex2f(e2), ex2f(e3)));
            acc[2] = f2add(acc[2], pk2(ex2f(e4), ex2f(e5)));
            acc[3] = f2add(acc[3], pk2(ex2f(e6), ex2f(e7)));
        }
        __syncthreads();
    }

#pragma unroll
    for (int off = 16; off; off >>= 1) {
#pragma unroll
        for (int r = 0; r < 4; r++)
            acc[r] = f2add(acc[r], __shfl_down_sync(0xffffffffu, acc[r], off));
    }
    if (lane == 0) {
        int idx4 = (base + r0) >> 2;
        if (MODE == 1) {
            float mx = NEG_INF;
#pragma unroll
            for (int r = 0; r < 4; r++) {
                float lo, hi; upk2(lo, hi, acc[r]);
                float lg = lg2f(rowv[r] / (EMD_EPS + (lo + hi)));
                g_lgL[base + r0 + r] = lg;
                mx = fmaxf(mx, lg);
            }
            g_rmL[idx4] = mx;
        } else {
            float mx2 = NEG_INF, mx3 = NEG_INF, mxN = 0.0f, tsum = 0.0f;
#pragma unroll
            for (int r = 0; r < 4; r++) {
                float lo, hi; upk2(lo, hi, acc[r]);
                float a = lo + hi;
                float rr   = rowv[r];
                float sumr = rr * a;
                float cons = fminf(rr / (sumr + EMD_EPS), 1.0f);
                float nrr  = fmaxf(0.0f, rr - sumr);
                float rat  = cons * rr;
                float lgr  = lg2f(rat);
                float l2r  = lg2f(nrr);
                g_lgR[base + r0 + r]  = lgr;
                g_ratR[base + r0 + r] = rat;
                g_rR[base + r0 + r]   = nrr;
                g_l2R[base + r0 + r]  = l2r;
                mx2 = fmaxf(mx2, l2r);
                mx3 = fmaxf(mx3, lgr);
                mxN = fmaxf(mxN, nrr);
                tsum += nrr;
            }
            g_rmR2[idx4] = mx2;
            g_rmR3[idx4] = mx3;
            g_rmNR[idx4] = mxN;
            if (accT) atomicAdd(&g_sumT[b], tsum);
        }
    }
}

// ---------------- P3(s8) + level-0 fused ----------------
__global__ void __launch_bounds__(128, 5) pass3_l0_kernel(float klg, int N) {
    __shared__ ulonglong2 s_xy[TS / 2];
    __shared__ ulonglong2 s_zw[TS / 2];
    __shared__ u64        s_lq[TS / 2];
    __shared__ u64        s_nr[TS / 2];
    __shared__ float s_cm[64];
    __shared__ float s_cn[64];
    __shared__ unsigned s_bm[4][2];
    const int b = blockIdx.y, base = b * N;
    const int t = threadIdx.x, warp = t >> 5, lane = t & 31;
    const int r0 = blockIdx.x * RPB + warp * 4;

    if (t < 64) {
        float m = NEG_INF, mn2 = 0.0f;
#pragma unroll
        for (int k = 0; k < 16; k++) {
            m   = fmaxf(m,   g_rmR3[b * (N / 4) + t * 16 + k]);
            mn2 = fmaxf(mn2, g_rmNR[b * (N / 4) + t * 16 + k]);
        }
        s_cm[t] = m; s_cn[t] = mn2;
    }

    u64 rx[4], ry[4], rz[4], rw[4], wa[4], cs[4], gp[4];
    float lgL[4], rlv[4];
    float4 A[4];
#pragma unroll
    for (int r = 0; r < 4; r++) {
        A[r] = g_p1[base + r0 + r];
        lgL[r] = g_lgL[base + r0 + r];
        rlv[r] = g_rL[base + r0 + r];
        rx[r] = pk2(-2.0f * A[r].x, -2.0f * A[r].x);
        ry[r] = pk2(-2.0f * A[r].y, -2.0f * A[r].y);
        rz[r] = pk2(-2.0f * A[r].z, -2.0f * A[r].z);
        rw[r] = pk2(A[r].w, A[r].w);
        wa[r] = 0ull; cs[r] = 0ull; gp[r] = 0ull;
    }
    float wmaxL = fmaxf(fmaxf(lgL[0], lgL[1]), fmaxf(lgL[2], lgL[3]));
    bool rowsDead = (wmaxL < -126.0f);
    __syncthreads();

    u64 wm;
    if (rowsDead) {
        __ballot_sync(0xffffffffu, 1);
        wm = ~0ull;
        if (lane == 0) { s_bm[warp][0] = 0xffffffffu; s_bm[warp][1] = 0xffffffffu; }
    } else {
        float wlx = fminf(fminf(A[0].x, A[1].x), fminf(A[2].x, A[3].x));
        float whx = fmaxf(fmaxf(A[0].x, A[1].x), fmaxf(A[2].x, A[3].x));
        float wly = fminf(fminf(A[0].y, A[1].y), fminf(A[2].y, A[3].y));
        float why = fmaxf(fmaxf(A[0].y, A[1].y), fmaxf(A[2].y, A[3].y));
        float wlz = fminf(fminf(A[0].z, A[1].z), fminf(A[2].z, A[3].z));
        float whz = fmaxf(fmaxf(A[0].z, A[1].z), fmaxf(A[2].z, A[3].z));
        float g0 = box_gap2(g_cb[1], b * 64 + lane,      wlx, wly, wlz, whx, why, whz);
        float g1 = box_gap2(g_cb[1], b * 64 + lane + 32, wlx, wly, wlz, whx, why, whz);
        bool k0 = (fmaf(klg, g0, s_cm[lane]      + wmaxL) < UF_TH) && (s_cn[lane]      == 0.0f);
        bool k1 = (fmaf(klg, g1, s_cm[lane + 32] + wmaxL) < UF_TH) && (s_cn[lane + 32] == 0.0f);
        unsigned lo = __ballot_sync(0xffffffffu, k0);
        unsigned hi = __ballot_sync(0xffffffffu, k1);
        wm = ((u64)hi << 32) | lo;
        if (lane == 0) { s_bm[warp][0] = lo; s_bm[warp][1] = hi; }
    }
    __syncthreads();
    u64 bm = (((u64)(s_bm[0][1] & s_bm[1][1] & s_bm[2][1] & s_bm[3][1])) << 32) |
             (u64)(s_bm[0][0] & s_bm[1][0] & s_bm[2][0] & s_bm[3][0]);
    const u64 klg2 = pk2(klg, klg);

    for (int c = 0; c < N; c += TS) {
        const int tb = c >> 6;
        if (((bm >> tb) & 0xFull) == 0xFull) continue;
        {
            int j = base + c + 2 * t;
            float4 q0 = g_p2[j], q1 = g_p2[j + 1];
            ulonglong2 xy; xy.x = pk2(q0.x, q1.x); xy.y = pk2(q0.y, q1.y);
            ulonglong2 zw; zw.x = pk2(q0.z, q1.z); zw.y = pk2(q0.w, q1.w);
            s_xy[t] = xy; s_zw[t] = zw;
            s_lq[t] = pk2(g_lgR[j], g_lgR[j + 1]);
            s_nr[t] = pk2(g_rR[j],  g_rR[j + 1]);
        }
        __syncthreads();
#pragma unroll
        for (int it = 0; it < TS / 64; it++) {
            if ((wm >> (tb + it)) & 1ull) continue;
            int p = it * 32 + lane;
            ulonglong2 xy = s_xy[p];
            ulonglong2 zw = s_zw[p];
            u64 lq2 = s_lq[p];
            u64 nr2 = s_nr[p];
            u64 d0 = f2fma(rz[0], zw.x, f2fma(ry[0], xy.y, f2fma(rx[0], xy.x, f2add(zw.y, rw[0]))));
            u64 d1 = f2fma(rz[1], zw.x, f2fma(ry[1], xy.y, f2fma(rx[1], xy.x, f2add(zw.y, rw[1]))));
            u64 d2 = f2fma(rz[2], zw.x, f2fma(ry[2], xy.y, f2fma(rx[2], xy.x, f2add(zw.y, rw[2]))));
            u64 d3 = f2fma(rz[3], zw.x, f2fma(ry[3], xy.y, f2fma(rx[3], xy.x, f2add(zw.y, rw[3]))));
            u64 a0 = f2fma(klg2, d0, lq2);
            u64 a1 = f2fma(klg2, d1, lq2);
            u64 a2 = f2fma(klg2, d2, lq2);
            u64 a3 = f2fma(klg2, d3, lq2);
            float f0, f1, f2v, f3v, f4, f5, f6, f7;
            upk2(f0, f1, a0); upk2(f2v, f3v, a1); upk2(f4, f5, a2); upk2(f6, f7, a3);
            float m0 = fmaxf(fmaxf(f0, f1), fmaxf(f2v, f3v));
            float m1 = fmaxf(fmaxf(f4, f5), fmaxf(f6, f7));
            bool liveW = !__all_sync(0xffffffffu, fmaxf(m0, m1) < UF_TH);
#pragma unroll
            for (int r = 0; r < 4; r++) {
                u64 dd = (r == 0) ? d0 : (r == 1) ? d1 : (r == 2) ? d2 : d3;
                float dl, dh; upk2(dl, dh, dd);
                float c0 = fmaxf(dl, 1e-20f), c1 = fmaxf(dh, 1e-20f);
                float s0 = sqrtf_apx(c0), s1 = sqrtf_apx(c1);
                u64 sq2 = pk2(s0, s1);
                gp[r] = f2fma(nr2, sq2, gp[r]);        // G_i += rR_j * sqrt(d)
                if (liveW) {
                    float av0, av1;
                    if (r == 0)      { av0 = f0;  av1 = f1; }
                    else if (r == 1) { av0 = f2v; av1 = f3v; }
                    else if (r == 2) { av0 = f4;  av1 = f5; }
                    else             { av0 = f6;  av1 = f7; }
                    float w0 = ex2f(av0), w1 = ex2f(av1);
                    u64 wv = pk2(w0, w1);
                    wa[r] = f2add(wa[r], wv);
                    cs[r] = f2fma(wv, sq2, cs[r]);
                }
            }
        }
        __syncthreads();
    }

#pragma unroll
    for (int off = 16; off; off >>= 1) {
#pragma unroll
        for (int r = 0; r < 4; r++) {
            wa[r] = f2add(wa[r], __shfl_down_sync(0xffffffffu, wa[r], off));
            cs[r] = f2add(cs[r], __shfl_down_sync(0xffffffffu, cs[r], off));
            gp[r] = f2add(gp[r], __shfl_down_sync(0xffffffffu, gp[r], off));
        }
    }
    if (lane == 0 && !rowsDead) {
        float cost = 0.0f, sl = 0.0f, slg = 0.0f;
#pragma unroll
        for (int r = 0; r < 4; r++) {
            float eL = ex2f(lgL[r]);
            float wl, wh; upk2(wl, wh, wa[r]);
            float cl, ch; upk2(cl, ch, cs[r]);
            float gl, gh; upk2(gl, gh, gp[r]);
            float rLnew = fmaxf(0.0f, rlv[r] - eL * (wl + wh));
            cost = fmaf(eL, cl + ch, cost);
            sl  += rLnew;
            slg  = fmaf(rLnew, gl + gh, slg);
        }
        atomicAdd(&g_cost, cost);
        atomicAdd(&g_sumL[b], sl);
        atomicAdd(&g_sumLG[b], slg);
    }
}

// ---------------- FUSED P3(s) + P1(s+1), product form ----------------
__global__ void __launch_bounds__(128, 5) fused31_kernel(float klg3, float klg1, int N) {
    __shared__ ulonglong2 s_xy[TS / 2];
    __shared__ ulonglong2 s_zw[TS / 2];
    __shared__ u64        s_rt[TS / 2];
    __shared__ u64        s_rr[TS / 2];
    __shared__ float s_cm3[64];
    __shared__ float s_cm1[64];
    __shared__ unsigned s_bm[4][2];
    const int b = blockIdx.y, base = b * N;
    const int t = threadIdx.x, warp = t >> 5, lane = t & 31;
    const int r0 = blockIdx.x * RPB + warp * 4;

    if (t < 64) {
        float m3 = NEG_INF, m1 = NEG_INF;
#pragma unroll
        for (int k = 0; k < 16; k++) {
            m3 = fmaxf(m3, g_rmR3[b * (N / 4) + t * 16 + k]);
            m1 = fmaxf(m1, g_rmR2[b * (N / 4) + t * 16 + k]);
        }
        s_cm3[t] = m3; s_cm1[t] = m1;
    }

    u64 rx[4], ry[4], rz[4], rw[4], wa[4], cs[4], acc[4];
    float lgL[4], rowv[4];
    float4 A[4];
#pragma unroll
    for (int r = 0; r < 4; r++) {
        A[r] = g_p1[base + r0 + r];
        lgL[r]  = g_lgL[base + r0 + r];
        rowv[r] = g_rL[base + r0 + r];
        float kx = klg1 * -2.0f * A[r].x, ky = klg1 * -2.0f * A[r].y, kz = klg1 * -2.0f * A[r].z;
        float kw = klg1 * A[r].w;
        rx[r] = pk2(kx, kx); ry[r] = pk2(ky, ky); rz[r] = pk2(kz, kz); rw[r] = pk2(kw, kw);
        wa[r] = 0ull; cs[r] = 0ull; acc[r] = 0ull;
    }
    float wmaxL = fmaxf(fmaxf(lgL[0], lgL[1]), fmaxf(lgL[2], lgL[3]));
    bool dead3 = (wmaxL < -126.0f);
    bool dead1 = (fmaxf(fmaxf(rowv[0], rowv[1]), fmaxf(rowv[2], rowv[3])) == 0.0f);
    __syncthreads();

    u64 wm3, wm1;
    {
        float wlx = fminf(fminf(A[0].x, A[1].x), fminf(A[2].x, A[3].x));
        float whx = fmaxf(fmaxf(A[0].x, A[1].x), fmaxf(A[2].x, A[3].x));
        float wly = fminf(fminf(A[0].y, A[1].y), fminf(A[2].y, A[3].y));
        float why = fmaxf(fmaxf(A[0].y, A[1].y), fmaxf(A[2].y, A[3].y));
        float wlz = fminf(fminf(A[0].z, A[1].z), fminf(A[2].z, A[3].z));
        float whz = fmaxf(fmaxf(A[0].z, A[1].z), fmaxf(A[2].z, A[3].z));
        float g0 = box_gap2(g_cb[1], b * 64 + lane,      wlx, wly, wlz, whx, why, whz);
        float g1 = box_gap2(g_cb[1], b * 64 + lane + 32, wlx, wly, wlz, whx, why, whz);
        bool k30 = dead3 || (fmaf(klg3, g0, s_cm3[lane]      + wmaxL) < UF_TH);
        bool k31 = dead3 || (fmaf(klg3, g1, s_cm3[lane + 32] + wmaxL) < UF_TH);
        bool k10 = dead1 || (fmaf(klg1, g0, s_cm1[lane])      < UF_TH);
        bool k11 = dead1 || (fmaf(klg1, g1, s_cm1[lane + 32]) < UF_TH);
        unsigned lo3 = __ballot_sync(0xffffffffu, k30);
        unsigned hi3 = __ballot_sync(0xffffffffu, k31);
        unsigned lo1 = __ballot_sync(0xffffffffu, k10);
        unsigned hi1 = __ballot_sync(0xffffffffu, k11);
        wm3 = ((u64)hi3 << 32) | lo3;
        wm1 = ((u64)hi1 << 32) | lo1;
        if (lane == 0) { s_bm[warp][0] = lo3 & lo1; s_bm[warp][1] = hi3 & hi1; }
    }
    __syncthreads();
    u64 bm = (((u64)(s_bm[0][1] & s_bm[1][1] & s_bm[2][1] & s_bm[3][1])) << 32) |
             (u64)(s_bm[0][0] & s_bm[1][0] & s_bm[2][0] & s_bm[3][0]);
    const float inv_klg1 = 1.0f / klg1;

    for (int c = 0; c < N; c += TS) {
        const int tb = c >> 6;
        if (((bm >> tb) & 0xFull) == 0xFull) continue;
        {
            int j = base + c + 2 * t;
            float4 q0 = g_p2[j], q1 = g_p2[j + 1];
            ulonglong2 xy; xy.x = pk2(q0.x, q1.x); xy.y = pk2(q0.y, q1.y);
            ulonglong2 zw; zw.x = pk2(q0.z, q1.z); zw.y = pk2(klg1 * q0.w, klg1 * q1.w);
            s_xy[t] = xy; s_zw[t] = zw;
            s_rt[t] = pk2(g_ratR[j], g_ratR[j + 1]);
            s_rr[t] = pk2(g_rR[j],   g_rR[j + 1]);
        }
        __syncthreads();
#pragma unroll
        for (int it = 0; it < TS / 64; it++) {
            bool skip3 = (wm3 >> (tb + it)) & 1ull;
            bool skip1 = (wm1 >> (tb + it)) & 1ull;
            if (skip3 && skip1) continue;
            int p = it * 32 + lane;
            ulonglong2 xy = s_xy[p];
            ulonglong2 zw = s_zw[p];
            u64 a0 = f2fma(rz[0], zw.x, f2fma(ry[0], xy.y, f2fma(rx[0], xy.x, f2add(zw.y, rw[0]))));
            u64 a1 = f2fma(rz[1], zw.x, f2fma(ry[1], xy.y, f2fma(rx[1], xy.x, f2add(zw.y, rw[1]))));
            u64 a2 = f2fma(rz[2], zw.x, f2fma(ry[2], xy.y, f2fma(rx[2], xy.x, f2add(zw.y, rw[2]))));
            u64 a3 = f2fma(rz[3], zw.x, f2fma(ry[3], xy.y, f2fma(rx[3], xy.x, f2add(zw.y, rw[3]))));
            float e0, e1, e2, e3, e4, e5, e6, e7;
            upk2(e0, e1, a0); upk2(e2, e3, a1); upk2(e4, e5, a2); upk2(e6, e7, a3);
            float mx = fmaxf(fmaxf(fmaxf(e0, e1), fmaxf(e2, e3)),
                             fmaxf(fmaxf(e4, e5), fmaxf(e6, e7)));
            if (__all_sync(0xffffffffu, mx < UF_TH)) continue;
            u64 u0 = pk2(ex2f(e0), ex2f(e1));
            u64 u1 = pk2(ex2f(e2), ex2f(e3));
            u64 u2 = pk2(ex2f(e4), ex2f(e5));
            u64 u3 = pk2(ex2f(e6), ex2f(e7));
            if (!skip1) {
                u64 rr2 = s_rr[p];
                acc[0] = f2fma(u0, rr2, acc[0]);
                acc[1] = f2fma(u1, rr2, acc[1]);
                acc[2] = f2fma(u2, rr2, acc[2]);
                acc[3] = f2fma(u3, rr2, acc[3]);
            }
            if (!skip3 && !__all_sync(0xffffffffu, mx < P3_TH)) {
                u64 rt2 = s_rt[p];
#pragma unroll
                for (int r = 0; r < 4; r++) {
                    u64 uu = (r == 0) ? u0 : (r == 1) ? u1 : (r == 2) ? u2 : u3;
                    u64 aa = (r == 0) ? a0 : (r == 1) ? a1 : (r == 2) ? a2 : a3;
                    u64 sq = f2mul(uu, uu);
                    u64 qd = f2mul(sq, sq);
                    u64 wv = f2mul(qd, rt2);
                    wa[r] = f2add(wa[r], wv);
                    float al, ah; upk2(al, ah, aa);
                    float dl = al * inv_klg1, dh = ah * inv_klg1;
                    float s0 = sqrtf_apx(fmaxf(dl, 1e-20f));
                    float s1 = sqrtf_apx(fmaxf(dh, 1e-20f));
                    cs[r] = f2fma(wv, pk2(s0, s1), cs[r]);
                }
            }
        }
        __syncthreads();
    }

#pragma unroll
    for (int off = 16; off; off >>= 1) {
#pragma unroll
        for (int r = 0; r < 4; r++) {
            wa[r]  = f2add(wa[r],  __shfl_down_sync(0xffffffffu, wa[r],  off));
            cs[r]  = f2add(cs[r],  __shfl_down_sync(0xffffffffu, cs[r],  off));
            acc[r] = f2add(acc[r], __shfl_down_sync(0xffffffffu, acc[r], off));
        }
    }
    if (lane == 0) {
        int idx4 = (base + r0) >> 2;
        float cost = 0.0f;
        float mx = NEG_INF;
#pragma unroll
        for (int r = 0; r < 4; r++) {
            int idx = base + r0 + r;
            float eL = ex2f(lgL[r]);
            float wl, wh; upk2(wl, wh, wa[r]);
            float cl, ch; upk2(cl, ch, cs[r]);
            float al, ah; upk2(al, ah, acc[r]);
            float rLnew = fmaxf(0.0f, rowv[r] - eL * (wl + wh));
            g_rL[idx] = rLnew;
            cost = fmaf(eL, cl + ch, cost);
            float lg = lg2f(rLnew / (EMD_EPS + (al + ah)));
            g_lgL[idx] = lg;
            mx = fmaxf(mx, lg);
        }
        g_rmL[idx4] = mx;
        if (!dead3) atomicAdd(&g_cost, cost);
    }
}

__global__ void final_kernel(float* out, float inv) {
    float total = g_cost;
#pragma unroll
    for (int b = 0; b < NB; b++) {
        float T = g_sumT[b];
        float scale = 1.0f / (EMD_EPS + T);
        float S = g_sumL[b] * scale;
        float kappa = fminf(1.0f / fmaxf(S, 1e-30f), 1.0f);
        total += scale * kappa * g_sumLG[b];
    }
    out[0] = total * inv;
}

extern "C" void kernel_launch(void* const* d_in, const int* in_sizes, int n_in,
                              void* d_out, int out_size) {
    const float* x1 = (const float*)d_in[0];
    const float* x2 = (const float*)d_in[1];
    const int B = NB;
    const int N = in_sizes[0] / (3 * B);   // 4096
    const int n = N, m = N;

    float multiL, multiR;
    if (n >= m) { multiL = 1.0f; multiR = (float)(n / m); }
    else        { multiL = (float)(m / n); multiR = 1.0f; }

    sort_kernel<<<dim3(B, 2), 512>>>(x1, x2, multiL, multiR, N);

    dim3 grid(N / RPB, B);
    const float LOG2E = 1.4426950408889634f;
    auto klg_of = [&](int s) { return -ldexpf(1.0f, 2 * (7 - s)) * LOG2E; };

    pass12_kernel<1><<<grid, 128>>>(klg_of(0), N, 0);   // initial P1 (s0)
    for (int s = 0; s < 9; s++) {
        float klg = klg_of(s);
        pass12_kernel<2><<<grid, 128>>>(klg, N, s == 8 ? 1 : 0);   // P2 (s)
        if (s < 8) {
            fused31_kernel<<<grid, 128>>>(klg, klg_of(s + 1), N);  // P3(s)+P1(s+1)
        } else {
            pass3_l0_kernel<<<grid, 128>>>(klg, N);                // P3(s8)+level0
        }
    }

    float mn = (float)((n < m ? n : m) * B);
    final_kernel<<<1, 1>>>((float*)d_out, 1.0f / mn);
}

// round 17
// speedup vs baseline: 1.8293x; 1.0253x over previous
#include <cuda_runtime.h>
#include <math.h>

// EMD approxmatch (Fan et al.) on GB300 — round 17.
// R16 + pre-packed f32x2 column/fold arrays (fills lose all transpose MOVs).
// Same grid/block/TS/masks/fusion as R16. 20 launches. B=4, N=4096.

#define EMD_EPS 1e-9f
#define NB 4
#define MAXBN (NB * 4096)
#define TS 256
#define RPB 16
#define UF_TH (-125.0f)
#define P3_TH (-31.5f)
#define NEG_INF (-__int_as_float(0x7f800000))

typedef unsigned long long u64;

__device__ float4 g_p1[MAXBN];          // sorted rows (x,y,z,|p|^2) x1
__device__ float4 g_p2[MAXBN];          // sorted rows x2
__device__ ulonglong2 g_c1xy[MAXBN/2];  // packed x1 columns {x01,y01}
__device__ ulonglong2 g_c1zw[MAXBN/2];  // {z01,w01}
__device__ ulonglong2 g_c2xy[MAXBN/2];  // packed x2 columns
__device__ ulonglong2 g_c2zw[MAXBN/2];
__device__ float  g_rL[MAXBN];          // row access
__device__ float  g_rR[MAXBN];          // row access
__device__ float  g_lgL[MAXBN];         // row access (fused/pass3 row loads)
__device__ u64    g_lgLp[MAXBN/2];      // packed col fold (P2)
__device__ u64    g_l2Rp[MAXBN/2];      // packed col fold (P1)
__device__ u64    g_lgRp[MAXBN/2];      // packed col fold (pass3_l0)
__device__ u64    g_ratRp[MAXBN/2];     // packed col (fused P3 side)
__device__ u64    g_rRp[MAXBN/2];       // packed col (fused P1 side, pass3_l0 G)
__device__ float  g_rmL[MAXBN/4];       // per-4-row max lgL (x1)
__device__ float  g_rmR2[MAXBN/4];      // per-4-row max l2R (x2)
__device__ float  g_rmR3[MAXBN/4];      // per-4-row max lgR (x2)
__device__ float  g_rmNR[MAXBN/4];      // per-4-row max remainR (x2)
__device__ float  g_cost;
__device__ float  g_sumT[NB];
__device__ float  g_sumL[NB];
__device__ float  g_sumLG[NB];
__device__ float4 g_cb[2][NB * 64 * 2];

__device__ __forceinline__ float ex2f(float x) {
    float y; asm("ex2.approx.ftz.f32 %0, %1;" : "=f"(y) : "f"(x)); return y;
}
__device__ __forceinline__ float lg2f(float x) {
    float y; asm("lg2.approx.ftz.f32 %0, %1;" : "=f"(y) : "f"(x)); return y;
}
__device__ __forceinline__ float sqrtf_apx(float x) {
    float y; asm("sqrt.approx.ftz.f32 %0, %1;" : "=f"(y) : "f"(x)); return y;
}
__device__ __forceinline__ u64 pk2(float a, float b) {
    u64 r; asm("mov.b64 %0, {%1, %2};" : "=l"(r) : "f"(a), "f"(b)); return r;
}
__device__ __forceinline__ void upk2(float& a, float& b, u64 v) {
    asm("mov.b64 {%0, %1}, %2;" : "=f"(a), "=f"(b) : "l"(v));
}
__device__ __forceinline__ u64 f2fma(u64 a, u64 b, u64 c) {
    u64 d; asm("fma.rn.f32x2 %0, %1, %2, %3;" : "=l"(d) : "l"(a), "l"(b), "l"(c)); return d;
}
__device__ __forceinline__ u64 f2add(u64 a, u64 b) {
    u64 d; asm("add.rn.f32x2 %0, %1, %2;" : "=l"(d) : "l"(a), "l"(b)); return d;
}
__device__ __forceinline__ u64 f2mul(u64 a, u64 b) {
    u64 d; asm("mul.rn.f32x2 %0, %1, %2;" : "=l"(d) : "l"(a), "l"(b)); return d;
}

__device__ __forceinline__ unsigned mort1(unsigned v) {
    return (v & 1u) | ((v & 2u) << 2) | ((v & 4u) << 4);
}

__device__ __forceinline__ float box_gap2(const float4* CB, int ci,
                                          float wlx, float wly, float wlz,
                                          float whx, float why, float whz) {
    float4 clo = __ldg(&CB[ci * 2]);
    float4 chi = __ldg(&CB[ci * 2 + 1]);
    float gx = fmaxf(0.0f, fmaxf(clo.x - whx, wlx - chi.x));
    float gy = fmaxf(0.0f, fmaxf(clo.y - why, wly - chi.y));
    float gz = fmaxf(0.0f, fmaxf(clo.z - whz, wlz - chi.z));
    return fmaf(gx, gx, fmaf(gy, gy, gz * gz));
}

// Counting sort by Morton cell id + packing + chunk bboxes. grid (B,2), block 512.
__global__ void sort_kernel(const float* __restrict__ x1, const float* __restrict__ x2,
                            float multiL, float multiR, int N) {
    __shared__ unsigned hist[512];
    __shared__ unsigned scan[512];
    __shared__ unsigned offs[512];
    const int b = blockIdx.x, side = blockIdx.y, t = threadIdx.x;
    const int warp = t >> 5, lane = t & 31;
    const float* px = (side ? x2 : x1) + (size_t)b * 3 * N;
    hist[t] = 0;
    __syncthreads();
    for (int i = t; i < N; i += 512) {
        float a = px[i], c = px[i + N], d = px[i + 2 * N];
        unsigned cx = (unsigned)min(7, max(0, (int)floorf(a + 4.0f)));
        unsigned cy = (unsigned)min(7, max(0, (int)floorf(c + 4.0f)));
        unsigned cz = (unsigned)min(7, max(0, (int)floorf(d + 4.0f)));
        unsigned cell = mort1(cx) | (mort1(cy) << 1) | (mort1(cz) << 2);
        atomicAdd(&hist[cell], 1u);
    }
    __syncthreads();
    scan[t] = hist[t];
    __syncthreads();
    for (int o = 1; o < 512; o <<= 1) {
        unsigned add = (t >= o) ? scan[t - o] : 0u;
        __syncthreads();
        scan[t] += add;
        __syncthreads();
    }
    offs[t] = scan[t] - hist[t];
    __syncthreads();
    for (int i = t; i < N; i += 512) {
        float a = px[i], c = px[i + N], d = px[i + 2 * N];
        unsigned cx = (unsigned)min(7, max(0, (int)floorf(a + 4.0f)));
        unsigned cy = (unsigned)min(7, max(0, (int)floorf(c + 4.0f)));
        unsigned cz = (unsigned)min(7, max(0, (int)floorf(d + 4.0f)));
        unsigned cell = mort1(cx) | (mort1(cy) << 1) | (mort1(cz) << 2);
        unsigned pos = atomicAdd(&offs[cell], 1u);
        int idx = b * N + (int)pos;
        float4 v = make_float4(a, c, d, a * a + c * c + d * d);
        if (side == 0) { g_p1[idx] = v; g_rL[idx] = multiL; }
        else           { g_p2[idx] = v; g_rR[idx] = multiR; }
    }
    if (side == 1) {
        float l2r = lg2f(multiR);
        u64 l2rp = pk2(l2r, l2r);
        for (int p = t; p < N / 2; p += 512) g_l2Rp[b * (N / 2) + p] = l2rp;
        for (int i = t; i < N / 4; i += 512) g_rmR2[b * (N / 4) + i] = l2r;
    }
    if (side == 0 && t == 0) {
        if (b == 0) g_cost = 0.0f;
        g_sumT[b] = 0.0f; g_sumL[b] = 0.0f; g_sumLG[b] = 0.0f;
    }
    __syncthreads();
    const float4* P = side ? g_p2 : g_p1;
    // pack columns
    {
        ulonglong2* CXY = side ? g_c2xy : g_c1xy;
        ulonglong2* CZW = side ? g_c2zw : g_c1zw;
        for (int p = t; p < N / 2; p += 512) {
            int j = b * N + 2 * p;
            float4 q0 = P[j], q1 = P[j + 1];
            ulonglong2 xy; xy.x = pk2(q0.x, q1.x); xy.y = pk2(q0.y, q1.y);
            ulonglong2 zw; zw.x = pk2(q0.z, q1.z); zw.y = pk2(q0.w, q1.w);
            CXY[b * (N / 2) + p] = xy;
            CZW[b * (N / 2) + p] = zw;
        }
    }
    float4* CB = g_cb[side];
    for (int c = warp; c < 64; c += 16) {
        int j = b * N + c * 64 + lane;
        float4 p0 = P[j], p1 = P[j + 32];
        float lx = fminf(p0.x, p1.x), hx = fmaxf(p0.x, p1.x);
        float ly = fminf(p0.y, p1.y), hy = fmaxf(p0.y, p1.y);
        float lz = fminf(p0.z, p1.z), hz = fmaxf(p0.z, p1.z);
#pragma unroll
        for (int o = 16; o; o >>= 1) {
            lx = fminf(lx, __shfl_xor_sync(0xffffffffu, lx, o));
            hx = fmaxf(hx, __shfl_xor_sync(0xffffffffu, hx, o));
            ly = fminf(ly, __shfl_xor_sync(0xffffffffu, ly, o));
            hy = fmaxf(hy, __shfl_xor_sync(0xffffffffu, hy, o));
            lz = fminf(lz, __shfl_xor_sync(0xffffffffu, lz, o));
            hz = fmaxf(hz, __shfl_xor_sync(0xffffffffu, hz, o));
        }
        if (lane == 0) {
            CB[(b * 64 + c) * 2]     = make_float4(lx, ly, lz, 0.0f);
            CB[(b * 64 + c) * 2 + 1] = make_float4(hx, hy, hz, 0.0f);
        }
    }
}

// ---------------- P1/P2 kernel ----------------
// MODE 1: rows=x1 (rL), cols=x2 packed, fold=g_l2Rp; writes lgL + lgLp + rmL.
// MODE 2: rows=x2 (rR), cols=x1 packed, fold=g_lgLp; writes lgRp,ratRp,rRp,l2Rp,rR + maxes.
template <int MODE>
__global__ void __launch_bounds__(128, 6) pass12_kernel(float klg, int N, int accT) {
    __shared__ ulonglong2 s_xy[TS / 2];
    __shared__ ulonglong2 s_zf[TS / 2];
    __shared__ float s_cm[64];
    __shared__ unsigned s_bm[4][2];
    const int b = blockIdx.y, base = b * N, pbase = b * (N / 2);
    const int t = threadIdx.x, warp = t >> 5, lane = t & 31;
    const int r0 = blockIdx.x * RPB + warp * 4;

    const float4* P        = (MODE == 1) ? g_p1 : g_p2;
    const ulonglong2* CXY  = (MODE == 1) ? g_c2xy : g_c1xy;
    const ulonglong2* CZW  = (MODE == 1) ? g_c2zw : g_c1zw;
    const float4* CB       = (MODE == 1) ? g_cb[1] : g_cb[0];
    const u64*    FOLD     = (MODE == 1) ? g_l2Rp : g_lgLp;
    const float*  RM       = (MODE == 1) ? g_rmR2 : g_rmL;

    if (t < 64) {
        float m = NEG_INF;
#pragma unroll
        for (int k = 0; k < 16; k++) m = fmaxf(m, RM[b * (N / 4) + t * 16 + k]);
        s_cm[t] = m;
    }

    u64 rx[4], ry[4], rz[4], rw[4], acc[4];
    float4 A[4];
    float rowv[4];
#pragma unroll
    for (int r = 0; r < 4; r++) {
        A[r] = P[base + r0 + r];
        rowv[r] = (MODE == 1) ? g_rL[base + r0 + r] : g_rR[base + r0 + r];
    }
#pragma unroll
    for (int r = 0; r < 4; r++) {
        float kx = klg * -2.0f * A[r].x, ky = klg * -2.0f * A[r].y, kz = klg * -2.0f * A[r].z;
        float kw = klg * A[r].w;
        rx[r] = pk2(kx, kx); ry[r] = pk2(ky, ky); rz[r] = pk2(kz, kz); rw[r] = pk2(kw, kw);
        acc[r] = 0ull;
    }
    bool rowsDead = (fmaxf(fmaxf(rowv[0], rowv[1]), fmaxf(rowv[2], rowv[3])) == 0.0f);
    __syncthreads();

    u64 wm;
    if (rowsDead) {
        __ballot_sync(0xffffffffu, 1);
        wm = ~0ull;
        if (lane == 0) { s_bm[warp][0] = 0xffffffffu; s_bm[warp][1] = 0xffffffffu; }
    } else {
        float wlx = fminf(fminf(A[0].x, A[1].x), fminf(A[2].x, A[3].x));
        float whx = fmaxf(fmaxf(A[0].x, A[1].x), fmaxf(A[2].x, A[3].x));
        float wly = fminf(fminf(A[0].y, A[1].y), fminf(A[2].y, A[3].y));
        float why = fmaxf(fmaxf(A[0].y, A[1].y), fmaxf(A[2].y, A[3].y));
        float wlz = fminf(fminf(A[0].z, A[1].z), fminf(A[2].z, A[3].z));
        float whz = fmaxf(fmaxf(A[0].z, A[1].z), fmaxf(A[2].z, A[3].z));
        float g0 = box_gap2(CB, b * 64 + lane,      wlx, wly, wlz, whx, why, whz);
        float g1 = box_gap2(CB, b * 64 + lane + 32, wlx, wly, wlz, whx, why, whz);
        bool k0 = fmaf(klg, g0, s_cm[lane])      < UF_TH;
        bool k1 = fmaf(klg, g1, s_cm[lane + 32]) < UF_TH;
        unsigned lo = __ballot_sync(0xffffffffu, k0);
        unsigned hi = __ballot_sync(0xffffffffu, k1);
        wm = ((u64)hi << 32) | lo;
        if (lane == 0) { s_bm[warp][0] = lo; s_bm[warp][1] = hi; }
    }
    __syncthreads();
    u64 bm = (((u64)(s_bm[0][1] & s_bm[1][1] & s_bm[2][1] & s_bm[3][1])) << 32) |
             (u64)(s_bm[0][0] & s_bm[1][0] & s_bm[2][0] & s_bm[3][0]);
    const u64 klg2 = pk2(klg, klg);

    for (int c = 0; c < N; c += TS) {
        const int tb = c >> 6;
        if (((bm >> tb) & 0xFull) == 0xFull) continue;
        {
            int p = pbase + c / 2 + t;
            ulonglong2 zw = CZW[p];
            ulonglong2 zf; zf.x = zw.x; zf.y = f2fma(klg2, zw.y, FOLD[p]);
            s_xy[t] = CXY[p]; s_zf[t] = zf;
        }
        __syncthreads();
#pragma unroll
        for (int it = 0; it < TS / 64; it++) {
            if ((wm >> (tb + it)) & 1ull) continue;
            int p = it * 32 + lane;
            ulonglong2 xy = s_xy[p];
            ulonglong2 zf = s_zf[p];
            u64 a0 = f2fma(rz[0], zf.x, f2fma(ry[0], xy.y, f2fma(rx[0], xy.x, f2add(zf.y, rw[0]))));
            u64 a1 = f2fma(rz[1], zf.x, f2fma(ry[1], xy.y, f2fma(rx[1], xy.x, f2add(zf.y, rw[1]))));
            u64 a2 = f2fma(rz[2], zf.x, f2fma(ry[2], xy.y, f2fma(rx[2], xy.x, f2add(zf.y, rw[2]))));
            u64 a3 = f2fma(rz[3], zf.x, f2fma(ry[3], xy.y, f2fma(rx[3], xy.x, f2add(zf.y, rw[3]))));
            float e0, e1, e2, e3, e4, e5, e6, e7;
            upk2(e0, e1, a0); upk2(e2, e3, a1); upk2(e4, e5, a2); upk2(e6, e7, a3);
            float m0 = fmaxf(fmaxf(e0, e1), fmaxf(e2, e3));
            float m1 = fmaxf(fmaxf(e4, e5), fmaxf(e6, e7));
            if (__all_sync(0xffffffffu, fmaxf(m0, m1) < UF_TH)) continue;
            acc[0] = f2add(acc[0], pk2(ex2f(e0), ex2f(e1)));
            acc[1] = f2add(acc[1], pk2(ex2f(e2), ex2f(e3)));
            acc[2] = f2add(acc[2], pk2(ex2f(e4), ex2f(e5)));
            acc[3] = f2add(acc[3], pk2(ex2f(e6), ex2f(e7)));
        }
        __syncthreads();
    }

#pragma unroll
    for (int off = 16; off; off >>= 1) {
#pragma unroll
        for (int r = 0; r < 4; r++)
            acc[r] = f2add(acc[r], __shfl_down_sync(0xffffffffu, acc[r], off));
    }
    if (lane == 0) {
        int idx4 = (base + r0) >> 2;
        int ip = (base + r0) >> 1;
        if (MODE == 1) {
            float lg[4];
            float mx = NEG_INF;
#pragma unroll
            for (int r = 0; r < 4; r++) {
                float lo, hi; upk2(lo, hi, acc[r]);
                lg[r] = lg2f(rowv[r] / (EMD_EPS + (lo + hi)));
                g_lgL[base + r0 + r] = lg[r];
                mx = fmaxf(mx, lg[r]);
            }
            g_lgLp[ip]     = pk2(lg[0], lg[1]);
            g_lgLp[ip + 1] = pk2(lg[2], lg[3]);
            g_rmL[idx4] = mx;
        } else {
            float lgr[4], l2r[4], rat[4], nrr[4];
            float mx2 = NEG_INF, mx3 = NEG_INF, mxN = 0.0f, tsum = 0.0f;
#pragma unroll
            for (int r = 0; r < 4; r++) {
                float lo, hi; upk2(lo, hi, acc[r]);
                float a = lo + hi;
                float rr   = rowv[r];
                float sumr = rr * a;
                float cons = fminf(rr / (sumr + EMD_EPS), 1.0f);
                nrr[r] = fmaxf(0.0f, rr - sumr);
                rat[r] = cons * rr;
                lgr[r] = lg2f(rat[r]);
                l2r[r] = lg2f(nrr[r]);
                g_rR[base + r0 + r] = nrr[r];
                mx2 = fmaxf(mx2, l2r[r]);
                mx3 = fmaxf(mx3, lgr[r]);
                mxN = fmaxf(mxN, nrr[r]);
                tsum += nrr[r];
            }
            g_lgRp[ip]      = pk2(lgr[0], lgr[1]);
            g_lgRp[ip + 1]  = pk2(lgr[2], lgr[3]);
            g_ratRp[ip]     = pk2(rat[0], rat[1]);
            g_ratRp[ip + 1] = pk2(rat[2], rat[3]);
            g_rRp[ip]       = pk2(nrr[0], nrr[1]);
            g_rRp[ip + 1]   = pk2(nrr[2], nrr[3]);
            g_l2Rp[ip]      = pk2(l2r[0], l2r[1]);
            g_l2Rp[ip + 1]  = pk2(l2r[2], l2r[3]);
            g_rmR2[idx4] = mx2;
            g_rmR3[idx4] = mx3;
            g_rmNR[idx4] = mxN;
            if (accT) atomicAdd(&g_sumT[b], tsum);
        }
    }
}

// ---------------- P3(s8) + level-0 fused ----------------
__global__ void __launch_bounds__(128, 5) pass3_l0_kernel(float klg, int N) {
    __shared__ ulonglong2 s_xy[TS / 2];
    __shared__ ulonglong2 s_zw[TS / 2];
    __shared__ u64        s_lq[TS / 2];
    __shared__ u64        s_nr[TS / 2];
    __shared__ float s_cm[64];
    __shared__ float s_cn[64];
    __shared__ unsigned s_bm[4][2];
    const int b = blockIdx.y, base = b * N, pbase = b * (N / 2);
    const int t = threadIdx.x, warp = t >> 5, lane = t & 31;
    const int r0 = blockIdx.x * RPB + warp * 4;

    if (t < 64) {
        float m = NEG_INF, mn2 = 0.0f;
#pragma unroll
        for (int k = 0; k < 16; k++) {
            m   = fmaxf(m,   g_rmR3[b * (N / 4) + t * 16 + k]);
            mn2 = fmaxf(mn2, g_rmNR[b * (N / 4) + t * 16 + k]);
        }
        s_cm[t] = m; s_cn[t] = mn2;
    }

    u64 rx[4], ry[4], rz[4], rw[4], wa[4], cs[4], gp[4];
    float lgL[4], rlv[4];
    float4 A[4];
#pragma unroll
    for (int r = 0; r < 4; r++) {
        A[r] = g_p1[base + r0 + r];
        lgL[r] = g_lgL[base + r0 + r];
        rlv[r] = g_rL[base + r0 + r];
        rx[r] = pk2(-2.0f * A[r].x, -2.0f * A[r].x);
        ry[r] = pk2(-2.0f * A[r].y, -2.0f * A[r].y);
        rz[r] = pk2(-2.0f * A[r].z, -2.0f * A[r].z);
        rw[r] = pk2(A[r].w, A[r].w);
        wa[r] = 0ull; cs[r] = 0ull; gp[r] = 0ull;
    }
    float wmaxL = fmaxf(fmaxf(lgL[0], lgL[1]), fmaxf(lgL[2], lgL[3]));
    bool rowsDead = (wmaxL < -126.0f);
    __syncthreads();

    u64 wm;
    if (rowsDead) {
        __ballot_sync(0xffffffffu, 1);
        wm = ~0ull;
        if (lane == 0) { s_bm[warp][0] = 0xffffffffu; s_bm[warp][1] = 0xffffffffu; }
    } else {
        float wlx = fminf(fminf(A[0].x, A[1].x), fminf(A[2].x, A[3].x));
        float whx = fmaxf(fmaxf(A[0].x, A[1].x), fmaxf(A[2].x, A[3].x));
        float wly = fminf(fminf(A[0].y, A[1].y), fminf(A[2].y, A[3].y));
        float why = fmaxf(fmaxf(A[0].y, A[1].y), fmaxf(A[2].y, A[3].y));
        float wlz = fminf(fminf(A[0].z, A[1].z), fminf(A[2].z, A[3].z));
        float whz = fmaxf(fmaxf(A[0].z, A[1].z), fmaxf(A[2].z, A[3].z));
        float g0 = box_gap2(g_cb[1], b * 64 + lane,      wlx, wly, wlz, whx, why, whz);
        float g1 = box_gap2(g_cb[1], b * 64 + lane + 32, wlx, wly, wlz, whx, why, whz);
        bool k0 = (fmaf(klg, g0, s_cm[lane]      + wmaxL) < UF_TH) && (s_cn[lane]      == 0.0f);
        bool k1 = (fmaf(klg, g1, s_cm[lane + 32] + wmaxL) < UF_TH) && (s_cn[lane + 32] == 0.0f);
        unsigned lo = __ballot_sync(0xffffffffu, k0);
        unsigned hi = __ballot_sync(0xffffffffu, k1);
        wm = ((u64)hi << 32) | lo;
        if (lane == 0) { s_bm[warp][0] = lo; s_bm[warp][1] = hi; }
    }
    __syncthreads();
    u64 bm = (((u64)(s_bm[0][1] & s_bm[1][1] & s_bm[2][1] & s_bm[3][1])) << 32) |
             (u64)(s_bm[0][0] & s_bm[1][0] & s_bm[2][0] & s_bm[3][0]);
    const u64 klg2 = pk2(klg, klg);

    for (int c = 0; c < N; c += TS) {
        const int tb = c >> 6;
        if (((bm >> tb) & 0xFull) == 0xFull) continue;
        {
            int p = pbase + c / 2 + t;
            s_xy[t] = g_c2xy[p];
            s_zw[t] = g_c2zw[p];
            s_lq[t] = g_lgRp[p];
            s_nr[t] = g_rRp[p];
        }
        __syncthreads();
#pragma unroll
        for (int it = 0; it < TS / 64; it++) {
            if ((wm >> (tb + it)) & 1ull) continue;
            int p = it * 32 + lane;
            ulonglong2 xy = s_xy[p];
            ulonglong2 zw = s_zw[p];
            u64 lq2 = s_lq[p];
            u64 nr2 = s_nr[p];
            u64 d0 = f2fma(rz[0], zw.x, f2fma(ry[0], xy.y, f2fma(rx[0], xy.x, f2add(zw.y, rw[0]))));
            u64 d1 = f2fma(rz[1], zw.x, f2fma(ry[1], xy.y, f2fma(rx[1], xy.x, f2add(zw.y, rw[1]))));
            u64 d2 = f2fma(rz[2], zw.x, f2fma(ry[2], xy.y, f2fma(rx[2], xy.x, f2add(zw.y, rw[2]))));
            u64 d3 = f2fma(rz[3], zw.x, f2fma(ry[3], xy.y, f2fma(rx[3], xy.x, f2add(zw.y, rw[3]))));
            u64 a0 = f2fma(klg2, d0, lq2);
            u64 a1 = f2fma(klg2, d1, lq2);
            u64 a2 = f2fma(klg2, d2, lq2);
            u64 a3 = f2fma(klg2, d3, lq2);
            float f0, f1, f2v, f3v, f4, f5, f6, f7;
            upk2(f0, f1, a0); upk2(f2v, f3v, a1); upk2(f4, f5, a2); upk2(f6, f7, a3);
            float m0 = fmaxf(fmaxf(f0, f1), fmaxf(f2v, f3v));
            float m1 = fmaxf(fmaxf(f4, f5), fmaxf(f6, f7));
            bool liveW = !__all_sync(0xffffffffu, fmaxf(m0, m1) < UF_TH);
#pragma unroll
            for (int r = 0; r < 4; r++) {
                u64 dd = (r == 0) ? d0 : (r == 1) ? d1 : (r == 2) ? d2 : d3;
                float dl, dh; upk2(dl, dh, dd);
                float c0 = fmaxf(dl, 1e-20f), c1 = fmaxf(dh, 1e-20f);
                float s0 = sqrtf_apx(c0), s1 = sqrtf_apx(c1);
                u64 sq2 = pk2(s0, s1);
                gp[r] = f2fma(nr2, sq2, gp[r]);
                if (liveW) {
                    float av0, av1;
                    if (r == 0)      { av0 = f0;  av1 = f1; }
                    else if (r == 1) { av0 = f2v; av1 = f3v; }
                    else if (r == 2) { av0 = f4;  av1 = f5; }
                    else             { av0 = f6;  av1 = f7; }
                    float w0 = ex2f(av0), w1 = ex2f(av1);
                    u64 wv = pk2(w0, w1);
                    wa[r] = f2add(wa[r], wv);
                    cs[r] = f2fma(wv, sq2, cs[r]);
                }
            }
        }
        __syncthreads();
    }

#pragma unroll
    for (int off = 16; off; off >>= 1) {
#pragma unroll
        for (int r = 0; r < 4; r++) {
            wa[r] = f2add(wa[r], __shfl_down_sync(0xffffffffu, wa[r], off));
            cs[r] = f2add(cs[r], __shfl_down_sync(0xffffffffu, cs[r], off));
            gp[r] = f2add(gp[r], __shfl_down_sync(0xffffffffu, gp[r], off));
        }
    }
    if (lane == 0 && !rowsDead) {
        float cost = 0.0f, sl = 0.0f, slg = 0.0f;
#pragma unroll
        for (int r = 0; r < 4; r++) {
            float eL = ex2f(lgL[r]);
            float wl, wh; upk2(wl, wh, wa[r]);
            float cl, ch; upk2(cl, ch, cs[r]);
            float gl, gh; upk2(gl, gh, gp[r]);
            float rLnew = fmaxf(0.0f, rlv[r] - eL * (wl + wh));
            cost = fmaf(eL, cl + ch, cost);
            sl  += rLnew;
            slg  = fmaf(rLnew, gl + gh, slg);
        }
        atomicAdd(&g_cost, cost);
        atomicAdd(&g_sumL[b], sl);
        atomicAdd(&g_sumLG[b], slg);
    }
}

// ---------------- FUSED P3(s) + P1(s+1), product form ----------------
__global__ void __launch_bounds__(128, 5) fused31_kernel(float klg3, float klg1, int N) {
    __shared__ ulonglong2 s_xy[TS / 2];
    __shared__ ulonglong2 s_zf[TS / 2];   // {z01, klg1*w01}
    __shared__ u64        s_rt[TS / 2];
    __shared__ u64        s_rr[TS / 2];
    __shared__ float s_cm3[64];
    __shared__ float s_cm1[64];
    __shared__ unsigned s_bm[4][2];
    const int b = blockIdx.y, base = b * N, pbase = b * (N / 2);
    const int t = threadIdx.x, warp = t >> 5, lane = t & 31;
    const int r0 = blockIdx.x * RPB + warp * 4;

    if (t < 64) {
        float m3 = NEG_INF, m1 = NEG_INF;
#pragma unroll
        for (int k = 0; k < 16; k++) {
            m3 = fmaxf(m3, g_rmR3[b * (N / 4) + t * 16 + k]);
            m1 = fmaxf(m1, g_rmR2[b * (N / 4) + t * 16 + k]);
        }
        s_cm3[t] = m3; s_cm1[t] = m1;
    }

    u64 rx[4], ry[4], rz[4], rw[4], wa[4], cs[4], acc[4];
    float lgL[4], rowv[4];
    float4 A[4];
#pragma unroll
    for (int r = 0; r < 4; r++) {
        A[r] = g_p1[base + r0 + r];
        lgL[r]  = g_lgL[base + r0 + r];
        rowv[r] = g_rL[base + r0 + r];
        float kx = klg1 * -2.0f * A[r].x, ky = klg1 * -2.0f * A[r].y, kz = klg1 * -2.0f * A[r].z;
        float kw = klg1 * A[r].w;
        rx[r] = pk2(kx, kx); ry[r] = pk2(ky, ky); rz[r] = pk2(kz, kz); rw[r] = pk2(kw, kw);
        wa[r] = 0ull; cs[r] = 0ull; acc[r] = 0ull;
    }
    float wmaxL = fmaxf(fmaxf(lgL[0], lgL[1]), fmaxf(lgL[2], lgL[3]));
    bool dead3 = (wmaxL < -126.0f);
    bool dead1 = (fmaxf(fmaxf(rowv[0], rowv[1]), fmaxf(rowv[2], rowv[3])) == 0.0f);
    __syncthreads();

    u64 wm3, wm1;
    {
        float wlx = fminf(fminf(A[0].x, A[1].x), fminf(A[2].x, A[3].x));
        float whx = fmaxf(fmaxf(A[0].x, A[1].x), fmaxf(A[2].x, A[3].x));
        float wly = fminf(fminf(A[0].y, A[1].y), fminf(A[2].y, A[3].y));
        float why = fmaxf(fmaxf(A[0].y, A[1].y), fmaxf(A[2].y, A[3].y));
        float wlz = fminf(fminf(A[0].z, A[1].z), fminf(A[2].z, A[3].z));
        float whz = fmaxf(fmaxf(A[0].z, A[1].z), fmaxf(A[2].z, A[3].z));
        float g0 = box_gap2(g_cb[1], b * 64 + lane,      wlx, wly, wlz, whx, why, whz);
        float g1 = box_gap2(g_cb[1], b * 64 + lane + 32, wlx, wly, wlz, whx, why, whz);
        bool k30 = dead3 || (fmaf(klg3, g0, s_cm3[lane]      + wmaxL) < UF_TH);
        bool k31 = dead3 || (fmaf(klg3, g1, s_cm3[lane + 32] + wmaxL) < UF_TH);
        bool k10 = dead1 || (fmaf(klg1, g0, s_cm1[lane])      < UF_TH);
        bool k11 = dead1 || (fmaf(klg1, g1, s_cm1[lane + 32]) < UF_TH);
        unsigned lo3 = __ballot_sync(0xffffffffu, k30);
        unsigned hi3 = __ballot_sync(0xffffffffu, k31);
        unsigned lo1 = __ballot_sync(0xffffffffu, k10);
        unsigned hi1 = __ballot_sync(0xffffffffu, k11);
        wm3 = ((u64)hi3 << 32) | lo3;
        wm1 = ((u64)hi1 << 32) | lo1;
        if (lane == 0) { s_bm[warp][0] = lo3 & lo1; s_bm[warp][1] = hi3 & hi1; }
    }
    __syncthreads();
    u64 bm = (((u64)(s_bm[0][1] & s_bm[1][1] & s_bm[2][1] & s_bm[3][1])) << 32) |
             (u64)(s_bm[0][0] & s_bm[1][0] & s_bm[2][0] & s_bm[3][0]);
    const float inv_klg1 = 1.0f / klg1;
    const u64 klg1_2 = pk2(klg1, klg1);

    for (int c = 0; c < N; c += TS) {
        const int tb = c >> 6;
        if (((bm >> tb) & 0xFull) == 0xFull) continue;
        {
            int p = pbase + c / 2 + t;
            ulonglong2 zw = g_c2zw[p];
            ulonglong2 zf; zf.x = zw.x; zf.y = f2mul(klg1_2, zw.y);
            s_xy[t] = g_c2xy[p]; s_zf[t] = zf;
            s_rt[t] = g_ratRp[p];
            s_rr[t] = g_rRp[p];
        }
        __syncthreads();
#pragma unroll
        for (int it = 0; it < TS / 64; it++) {
            bool skip3 = (wm3 >> (tb + it)) & 1ull;
            bool skip1 = (wm1 >> (tb + it)) & 1ull;
            if (skip3 && skip1) continue;
            int p = it * 32 + lane;
            ulonglong2 xy = s_xy[p];
            ulonglong2 zf = s_zf[p];
            u64 a0 = f2fma(rz[0], zf.x, f2fma(ry[0], xy.y, f2fma(rx[0], xy.x, f2add(zf.y, rw[0]))));
            u64 a1 = f2fma(rz[1], zf.x, f2fma(ry[1], xy.y, f2fma(rx[1], xy.x, f2add(zf.y, rw[1]))));
            u64 a2 = f2fma(rz[2], zf.x, f2fma(ry[2], xy.y, f2fma(rx[2], xy.x, f2add(zf.y, rw[2]))));
            u64 a3 = f2fma(rz[3], zf.x, f2fma(ry[3], xy.y, f2fma(rx[3], xy.x, f2add(zf.y, rw[3]))));
            float e0, e1, e2, e3, e4, e5, e6, e7;
            upk2(e0, e1, a0); upk2(e2, e3, a1); upk2(e4, e5, a2); upk2(e6, e7, a3);
            float mx = fmaxf(fmaxf(fmaxf(e0, e1), fmaxf(e2, e3)),
                             fmaxf(fmaxf(e4, e5), fmaxf(e6, e7)));
            if (__all_sync(0xffffffffu, mx < UF_TH)) continue;
            u64 u0 = pk2(ex2f(e0), ex2f(e1));
            u64 u1 = pk2(ex2f(e2), ex2f(e3));
            u64 u2 = pk2(ex2f(e4), ex2f(e5));
            u64 u3 = pk2(ex2f(e6), ex2f(e7));
            if (!skip1) {
                u64 rr2 = s_rr[p];
                acc[0] = f2fma(u0, rr2, acc[0]);
                acc[1] = f2fma(u1, rr2, acc[1]);
                acc[2] = f2fma(u2, rr2, acc[2]);
                acc[3] = f2fma(u3, rr2, acc[3]);
            }
            if (!skip3 && !__all_sync(0xffffffffu, mx < P3_TH)) {
                u64 rt2 = s_rt[p];
#pragma unroll
                for (int r = 0; r < 4; r++) {
                    u64 uu = (r == 0) ? u0 : (r == 1) ? u1 : (r == 2) ? u2 : u3;
                    u64 aa = (r == 0) ? a0 : (r == 1) ? a1 : (r == 2) ? a2 : a3;
                    u64 sq = f2mul(uu, uu);
                    u64 qd = f2mul(sq, sq);
                    u64 wv = f2mul(qd, rt2);
                    wa[r] = f2add(wa[r], wv);
                    float al, ah; upk2(al, ah, aa);
                    float dl = al * inv_klg1, dh = ah * inv_klg1;
                    float s0 = sqrtf_apx(fmaxf(dl, 1e-20f));
                    float s1 = sqrtf_apx(fmaxf(dh, 1e-20f));
                    cs[r] = f2fma(wv, pk2(s0, s1), cs[r]);
                }
            }
        }
        __syncthreads();
    }

#pragma unroll
    for (int off = 16; off; off >>= 1) {
#pragma unroll
        for (int r = 0; r < 4; r++) {
            wa[r]  = f2add(wa[r],  __shfl_down_sync(0xffffffffu, wa[r],  off));
            cs[r]  = f2add(cs[r],  __shfl_down_sync(0xffffffffu, cs[r],  off));
            acc[r] = f2add(acc[r], __shfl_down_sync(0xffffffffu, acc[r], off));
        }
    }
    if (lane == 0) {
        int idx4 = (base + r0) >> 2;
        int ip = (base + r0) >> 1;
        float cost = 0.0f;
        float lg[4];
        float mx = NEG_INF;
#pragma unroll
        for (int r = 0; r < 4; r++) {
            int idx = base + r0 + r;
            float eL = ex2f(lgL[r]);
            float wl, wh; upk2(wl, wh, wa[r]);
            float cl, ch; upk2(cl, ch, cs[r]);
            float al, ah; upk2(al, ah, acc[r]);
            float rLnew = fmaxf(0.0f, rowv[r] - eL * (wl + wh));
            g_rL[idx] = rLnew;
            cost = fmaf(eL, cl + ch, cost);
            lg[r] = lg2f(rLnew / (EMD_EPS + (al + ah)));
            g_lgL[idx] = lg[r];
            mx = fmaxf(mx, lg[r]);
        }
        g_lgLp[ip]     = pk2(lg[0], lg[1]);
        g_lgLp[ip + 1] = pk2(lg[2], lg[3]);
        g_rmL[idx4] = mx;
        if (!dead3) atomicAdd(&g_cost, cost);
    }
}

__global__ void final_kernel(float* out, float inv) {
    float total = g_cost;
#pragma unroll
    for (int b = 0; b < NB; b++) {
        float T = g_sumT[b];
        float scale = 1.0f / (EMD_EPS + T);
        float S = g_sumL[b] * scale;
        float kappa = fminf(1.0f / fmaxf(S, 1e-30f), 1.0f);
        total += scale * kappa * g_sumLG[b];
    }
    out[0] = total * inv;
}

extern "C" void kernel_launch(void* const* d_in, const int* in_sizes, int n_in,
                              void* d_out, int out_size) {
    const float* x1 = (const float*)d_in[0];
    const float* x2 = (const float*)d_in[1];
    const int B = NB;
    const int N = in_sizes[0] / (3 * B);   // 4096
    const int n = N, m = N;

    float multiL, multiR;
    if (n >= m) { multiL = 1.0f; multiR = (float)(n / m); }
    else        { multiL = (float)(m / n); multiR = 1.0f; }

    sort_kernel<<<dim3(B, 2), 512>>>(x1, x2, multiL, multiR, N);

    dim3 grid(N / RPB, B);
    const float LOG2E = 1.4426950408889634f;
    auto klg_of = [&](int s) { return -ldexpf(1.0f, 2 * (7 - s)) * LOG2E; };

    pass12_kernel<1><<<grid, 128>>>(klg_of(0), N, 0);   // initial P1 (s0)
    for (int s = 0; s < 9; s++) {
        float klg = klg_of(s);
        pass12_kernel<2><<<grid, 128>>>(klg, N, s == 8 ? 1 : 0);   // P2 (s)
        if (s < 8) {
            fused31_kernel<<<grid, 128>>>(klg, klg_of(s + 1), N);  // P3(s)+P1(s+1)
        } else {
            pass3_l0_kernel<<<grid, 128>>>(klg, N);                // P3(s8)+level0
        }
    }

    float mn = (float)((n < m ? n : m) * B);
    final_kernel<<<1, 1>>>((float*)d_out, 1.0f / mn);
}